// round 3
// baseline (speedup 1.0000x reference)
#include <cuda_runtime.h>
#include <math.h>

#define Bz 32
#define Hh 512
#define Ll 2
#define Vv 10000
#define Tt 20
#define Ss 49
#define G4 2048
#define NBLK 148
#define NTILES 313
#define SMEM_FLOATS (2*Bz*Hh + 512)
#define SMEM_BYTES (SMEM_FLOATS * 4)

// ---------------- device scratch ----------------
__device__ float g_keysT[Bz*Ss*Hh];     // [b][s][d]
__device__ float g_values[Bz*Hh*Ss];    // [b][d][s]
__device__ float g_h[Ll*Bz*Hh];         // post-cell hidden
__device__ float g_hF[Ll*Bz*Hh];        // post-attention hidden
__device__ float g_c[Ll*Bz*Hh];
__device__ float g_emb[Bz*Hh];
__device__ float g_pmax[NTILES*Bz];
__device__ int   g_pidx[NTILES*Bz];
__device__ int   g_tok[Bz];
__device__ float g_WihT[Ll*Hh*G4];      // [l][k][j]
__device__ float g_WhhT[Ll*Hh*G4];
__device__ float g_projWT[Hh*Vv];       // [d][v]
__device__ float g_WqT[Hh*Hh];          // [k][d]
__device__ float g_hattWT[2*Hh*Hh];     // [k][d]
__device__ unsigned g_bar_count = 0;
__device__ volatile unsigned g_bar_gen = 0;

__device__ __forceinline__ float sigm(float x) { return 1.0f / (1.0f + expf(-x)); }

// ---------------- grid barrier (release/acquire) ----------------
__device__ __forceinline__ void gsync() {
    __syncthreads();
    if (threadIdx.x == 0) {
        unsigned gen = g_bar_gen;
        __threadfence();
        unsigned t = atomicAdd(&g_bar_count, 1u);
        if (t == NBLK - 1) {
            g_bar_count = 0u;
            __threadfence();
            g_bar_gen = gen + 1u;
        } else {
            while (g_bar_gen == gen) {
                unsigned ns = 40;
                asm volatile("nanosleep.u32 %0;" :: "r"(ns));
            }
        }
        __threadfence();
    }
    __syncthreads();
}

// ---------------- phase A/B: gates + cell for one layer (blocks 0..127) ----------------
__device__ void phase_gates(int l, float* S, const float* __restrict__ bih,
                            const float* __restrict__ bhh) {
    int tid = threadIdx.x, x = blockIdx.x;
    float* sA = S;
    float* sB = S + Bz*Hh;
    float* sg = S + 2*Bz*Hh;
    const float4* xs = (const float4*)((l == 0) ? g_emb : g_h);   // layer input
    const float4* hs = (const float4*)(g_hF + l*Bz*Hh);           // recurrent (post-attn)
    float4* A4 = (float4*)sA; float4* B4 = (float4*)sB;
    for (int i = tid; i < Bz*Hh/4; i += 256) { A4[i] = xs[i]; B4[i] = hs[i]; }
    __syncthreads();

    int cl = tid & 15, bg = tid >> 4;
    int qq = cl & 3, gg = cl >> 2;
    int gi = x*4 + qq;
    int j  = gg*512 + gi;
    int b0 = bg*2;
    float acc0 = 0.f, acc1 = 0.f;
    const float* WA = g_WihT + l*(Hh*G4);
    const float* WB = g_WhhT + l*(Hh*G4);
    const float* a0 = &sA[b0*Hh]; const float* a1 = &sA[(b0+1)*Hh];
    const float* h0 = &sB[b0*Hh]; const float* h1 = &sB[(b0+1)*Hh];
#pragma unroll 4
    for (int k = 0; k < Hh; k += 4) {
        const float* wp = &WA[k*G4 + j];
        float w0 = wp[0], w1 = wp[G4], w2 = wp[2*G4], w3 = wp[3*G4];
        float4 v0 = *(const float4*)&a0[k];
        float4 v1 = *(const float4*)&a1[k];
        acc0 += v0.x*w0 + v0.y*w1 + v0.z*w2 + v0.w*w3;
        acc1 += v1.x*w0 + v1.y*w1 + v1.z*w2 + v1.w*w3;
    }
#pragma unroll 4
    for (int k = 0; k < Hh; k += 4) {
        const float* wp = &WB[k*G4 + j];
        float w0 = wp[0], w1 = wp[G4], w2 = wp[2*G4], w3 = wp[3*G4];
        float4 v0 = *(const float4*)&h0[k];
        float4 v1 = *(const float4*)&h1[k];
        acc0 += v0.x*w0 + v0.y*w1 + v0.z*w2 + v0.w*w3;
        acc1 += v1.x*w0 + v1.y*w1 + v1.z*w2 + v1.w*w3;
    }
    sg[cl*32 + b0]     = acc0;
    sg[cl*32 + b0 + 1] = acc1;
    __syncthreads();

    if (tid < 128) {
        int q_ = tid >> 5, b = tid & 31;
        int gi2 = x*4 + q_;
        const float* bi = bih + l*G4; const float* bh = bhh + l*G4;
        float vi = sg[(0*4+q_)*32 + b] + bi[gi2]        + bh[gi2];
        float vf = sg[(1*4+q_)*32 + b] + bi[512 + gi2]  + bh[512 + gi2];
        float vg = sg[(2*4+q_)*32 + b] + bi[1024 + gi2] + bh[1024 + gi2];
        float vo = sg[(3*4+q_)*32 + b] + bi[1536 + gi2] + bh[1536 + gi2];
        int idx = (l*Bz + b)*Hh + gi2;
        float c  = g_c[idx];
        float cn = sigm(vf)*c + sigm(vi)*tanhf(vg);
        g_c[idx] = cn;
        g_h[idx] = sigm(vo)*tanhf(cn);
    }
}

// ---------------- logits tile: 32 v x (NB*8) b, + in-warp argmax partials ----------------
template <int NB>
__device__ void logit_tile(const float* __restrict__ sH, int tile, int bbase, int t,
                           const float* __restrict__ projb, float* __restrict__ res) {
    int tid = threadIdx.x;
    int vl = tid & 31, bg = tid >> 5;
    int v  = tile*32 + vl;
    int vc = (v < Vv) ? v : (Vv - 1);
    float acc[NB];
    const float* hp[NB];
#pragma unroll
    for (int i = 0; i < NB; i++) { acc[i] = 0.f; hp[i] = &sH[(bbase + bg*NB + i)*Hh]; }
#pragma unroll 2
    for (int d = 0; d < Hh; d += 4) {
        const float* wp = &g_projWT[d*Vv + vc];
        float w0 = wp[0], w1 = wp[Vv], w2 = wp[2*Vv], w3 = wp[3*Vv];
#pragma unroll
        for (int i = 0; i < NB; i++) {
            float4 a = *(const float4*)&hp[i][d];
            acc[i] += a.x*w0 + a.y*w1 + a.z*w2 + a.w*w3;
        }
    }
    float pb = projb[vc];
    bool valid = (v < Vv);
#pragma unroll
    for (int i = 0; i < NB; i++) {
        int b = bbase + bg*NB + i;
        float r = acc[i] + pb;
        if (valid) res[b*(Vv*Tt) + v*Tt + t] = r;
        float mv = valid ? r : -INFINITY;
        int   mi = v;
#pragma unroll
        for (int o = 16; o; o >>= 1) {
            float ov = __shfl_xor_sync(0xffffffffu, mv, o);
            int   oi = __shfl_xor_sync(0xffffffffu, mi, o);
            if (ov > mv || (ov == mv && oi < mi)) { mv = ov; mi = oi; }
        }
        if (vl == 0) { g_pmax[tile*32 + b] = mv; g_pidx[tile*32 + b] = mi; }
    }
}

// ---------------- phase C: logits + argmax partials (all 148 blocks) ----------------
__device__ void phase_logits(float* S, const float* __restrict__ projb,
                             float* __restrict__ res, int t) {
    int tid = threadIdx.x, blk = blockIdx.x;
    const float4* H4 = (const float4*)(g_h + Bz*Hh);   // layer-1 hidden
    float4* S4 = (float4*)S;
    for (int i = tid; i < Bz*Hh/4; i += 256) S4[i] = H4[i];
    __syncthreads();
    logit_tile<4>(S, blk,       0, t, projb, res);
    logit_tile<4>(S, blk + 148, 0, t, projb, res);
    if (blk < 34) {
        int tl = 296 + (blk >> 1);
        logit_tile<2>(S, tl, (blk & 1)*16, t, projb, res);
    }
}

// ---------------- phase E: attention + gated update (blocks 0..127) ----------------
__device__ void phase_attn(float* S, const float* __restrict__ bq,
                           const float* __restrict__ hattb) {
    int tid = threadIdx.x, blk = blockIdx.x;
    int p = blk >> 1, half = blk & 1;
    int l = p >> 5, b = p & 31;
    float* sh_h  = S;
    float* sh_q  = S + 512;
    float* sh_at = S + 1024;
    float* sh_sc = S + 1536;
    float* sh_w  = S + 1600;
    float* sh_inv = S + 1664;
    const float* hg = &g_h[(l*Bz + b)*Hh];
    sh_h[tid] = hg[tid]; sh_h[tid + 256] = hg[tid + 256];
    __syncthreads();

    // q = tanh(h @ Wq^T + bq)
#pragma unroll
    for (int rep = 0; rep < 2; rep++) {
        int d = rep*256 + tid;
        float acc = bq[d];
#pragma unroll 4
        for (int k = 0; k < Hh; k += 4) {
            float4 hv = *(const float4*)&sh_h[k];
            const float* wp = &g_WqT[k*Hh + d];
            acc += hv.x*wp[0] + hv.y*wp[Hh] + hv.z*wp[2*Hh] + hv.w*wp[3*Hh];
        }
        sh_q[d] = tanhf(acc);
    }
    __syncthreads();

    // scores
    int wd = tid >> 5, lane = tid & 31;
    for (int s = wd; s < Ss; s += 8) {
        const float* kp = &g_keysT[(b*Ss + s)*Hh];
        float ps = 0.f;
        for (int d = lane; d < Hh; d += 32) ps += sh_q[d]*kp[d];
#pragma unroll
        for (int o = 16; o; o >>= 1) ps += __shfl_xor_sync(0xffffffffu, ps, o);
        if (lane == 0) sh_sc[s] = ps * (1.0f/7.0f);
    }
    __syncthreads();
    if (tid < Ss) {
        float mx = sh_sc[0];
        for (int s = 1; s < Ss; s++) mx = fmaxf(mx, sh_sc[s]);
        sh_w[tid] = expf(sh_sc[tid] - mx);
    }
    __syncthreads();
    if (tid == 0) {
        float sum = 0.f;
        for (int s = 0; s < Ss; s++) sum += sh_w[s];
        sh_inv[0] = 1.0f / sum;
    }
    __syncthreads();

    // attn
#pragma unroll
    for (int rep = 0; rep < 2; rep++) {
        int d = rep*256 + tid;
        const float* vp = &g_values[(b*Hh + d)*Ss];
        float a = 0.f;
#pragma unroll
        for (int s = 0; s < Ss; s++) a += sh_w[s]*vp[s];
        sh_at[d] = a * sh_inv[0];
    }
    __syncthreads();

    // hF = tanh([attn, h] @ hattW^T + hattb), this block's 256 d-columns
    int d0 = half*256 + tid;
    float acc = hattb[d0];
#pragma unroll 4
    for (int k = 0; k < Hh; k += 4) {
        float4 av = *(const float4*)&sh_at[k];
        const float* wp = &g_hattWT[k*Hh + d0];
        acc += av.x*wp[0] + av.y*wp[Hh] + av.z*wp[2*Hh] + av.w*wp[3*Hh];
    }
#pragma unroll 4
    for (int k = 0; k < Hh; k += 4) {
        float4 hv = *(const float4*)&sh_h[k];
        const float* wp = &g_hattWT[(Hh + k)*Hh + d0];
        acc += hv.x*wp[0] + hv.y*wp[Hh] + hv.z*wp[2*Hh] + hv.w*wp[3*Hh];
    }
    g_hF[(l*Bz + b)*Hh + d0] = tanhf(acc);
}

// ---------------- phase E (block 128): argmax finalize + embedding gather ----------------
__device__ void phase_argmax(float* S, const float* __restrict__ embed) {
    int tid = threadIdx.x;
    float* sv = S;
    int* si = (int*)(S + 256);
    int b = tid & 31, j = tid >> 5;
    float mv = -INFINITY; int mi = 0;
    for (int tl = j; tl < NTILES; tl += 8) {
        float v = g_pmax[tl*32 + b]; int ix = g_pidx[tl*32 + b];
        if (v > mv || (v == mv && ix < mi)) { mv = v; mi = ix; }
    }
    sv[j*32 + b] = mv; si[j*32 + b] = mi;
    __syncthreads();
    if (tid < 32) {
        float bv = sv[b]; int bi = si[b];
        for (int j2 = 1; j2 < 8; j2++) {
            float v = sv[j2*32 + b]; int ix = si[j2*32 + b];
            if (v > bv || (v == bv && ix < bi)) { bv = v; bi = ix; }
        }
        g_tok[b] = bi;
    }
    __syncthreads();
    for (int i = tid; i < Bz*Hh; i += 256) {
        int bb = i >> 9, d = i & 511;
        g_emb[i] = embed[g_tok[bb]*Hh + d];
    }
}

// ---------------- persistent loop kernel ----------------
__global__ __launch_bounds__(256, 1)
void loop_kernel(const float* __restrict__ bih, const float* __restrict__ bhh,
                 const float* __restrict__ projb, const float* __restrict__ bq,
                 const float* __restrict__ hattb, const float* __restrict__ embed,
                 float* __restrict__ res) {
    extern __shared__ float S[];
    int blk = blockIdx.x;
    for (int t = 0; t < Tt - 1; t++) {
        if (blk < 128) phase_gates(0, S, bih, bhh);
        gsync();
        if (blk < 128) phase_gates(1, S, bih, bhh);
        gsync();
        phase_logits(S, projb, res, t + 1);
        gsync();
        if (blk < 128) phase_attn(S, bq, hattb);
        else if (blk == 128) phase_argmax(S, embed);
        gsync();
    }
}

// ---------------- prep kernels ----------------
__global__ void transpose_tiled(const float* __restrict__ src, float* __restrict__ dst,
                                int R, int C) {
    __shared__ float tile[32][33];
    int tx = threadIdx.x & 31, ty = threadIdx.x >> 5;
    int bx = blockIdx.x * 32, by = blockIdx.y * 32;
    for (int i = 0; i < 32; i += 8) {
        int r = by + ty + i, c = bx + tx;
        if (r < R && c < C) tile[ty + i][tx] = src[r*C + c];
    }
    __syncthreads();
    for (int i = 0; i < 32; i += 8) {
        int r = by + tx, c = bx + ty + i;   // dst[c*R + r]
        if (r < R && c < C) dst[c*R + r] = tile[tx][ty + i];
    }
}

__global__ void init_kernel(const float* __restrict__ pooled,
                            const float* __restrict__ embed,
                            const int* __restrict__ sos) {
    int i = blockIdx.x * 256 + threadIdx.x;
    if (i >= Bz * Hh) return;
    int d = i & (Hh - 1);
    g_emb[i] = embed[sos[0]*Hh + d];
    float p = pooled[i];
    g_hF[i] = p; g_hF[Bz*Hh + i] = p;
    g_c[i]  = p; g_c[Bz*Hh + i]  = p;
}

__global__ void kv_kernel(const float* __restrict__ chan,
                          const float* __restrict__ Wk, const float* __restrict__ bk,
                          const float* __restrict__ Wv, const float* __restrict__ bv) {
    int id = blockIdx.x * 256 + threadIdx.x;
    if (id >= Bz * Hh * Ss) return;
    int s = id % Ss;
    int d = (id / Ss) & (Hh - 1);
    int b = id / (Ss * Hh);
    const float* cp  = &chan[(b*Hh + d)*Ss];
    const float* wkp = &Wk[s*Ss];
    const float* wvp = &Wv[s*Ss];
    float aK = bk[s], aV = bv[s];
#pragma unroll
    for (int k = 0; k < Ss; k++) { float c = cp[k]; aK += c*wkp[k]; aV += c*wvp[k]; }
    g_keysT[(b*Ss + s)*Hh + d] = tanhf(aK);
    g_values[(b*Hh + d)*Ss + s] = tanhf(aV);
}

__global__ void t0_kernel(const float* __restrict__ projb, float* __restrict__ res) {
    int v = blockIdx.x * 256 + threadIdx.x;
    if (v >= Vv) return;
    float acc = projb[v];
    for (int d = 0; d < Hh; d++) acc += g_emb[d] * g_projWT[d*Vv + v];
    for (int b = 0; b < Bz; b++) res[b*(Vv*Tt) + v*Tt] = acc;
}

// ---------------- host launcher ----------------
extern "C" void kernel_launch(void* const* d_in, const int* in_sizes, int n_in,
                              void* d_out, int out_size) {
    const float* img    = (const float*)d_in[0];
    const float* pooled = (const float*)d_in[1];
    const float* embed  = (const float*)d_in[2];
    const float* Wq     = (const float*)d_in[3];
    const float* bq     = (const float*)d_in[4];
    const float* Wk     = (const float*)d_in[5];
    const float* bk     = (const float*)d_in[6];
    const float* Wv     = (const float*)d_in[7];
    const float* bv     = (const float*)d_in[8];
    const float* Wih    = (const float*)d_in[9];
    const float* Whh    = (const float*)d_in[10];
    const float* bih    = (const float*)d_in[11];
    const float* bhh    = (const float*)d_in[12];
    const float* projW  = (const float*)d_in[13];
    const float* projb  = (const float*)d_in[14];
    const float* hattW  = (const float*)d_in[15];
    const float* hattb  = (const float*)d_in[16];
    const int*   sos    = (const int*)d_in[17];
    float* res = (float*)d_out;

    void *pProjWT, *pWihT, *pWhhT, *pWqT, *pHattWT;
    cudaGetSymbolAddress(&pProjWT, g_projWT);
    cudaGetSymbolAddress(&pWihT,   g_WihT);
    cudaGetSymbolAddress(&pWhhT,   g_WhhT);
    cudaGetSymbolAddress(&pWqT,    g_WqT);
    cudaGetSymbolAddress(&pHattWT, g_hattWT);

    cudaFuncSetAttribute(loop_kernel, cudaFuncAttributeMaxDynamicSharedMemorySize, SMEM_BYTES);

    // coalesced tiled transposes
    transpose_tiled<<<dim3(16, 313), 256>>>(projW, (float*)pProjWT, Vv, Hh);
    transpose_tiled<<<dim3(16, 64),  256>>>(Wih,           (float*)pWihT,          G4, Hh);
    transpose_tiled<<<dim3(16, 64),  256>>>(Wih + G4*Hh,   (float*)pWihT + Hh*G4,  G4, Hh);
    transpose_tiled<<<dim3(16, 64),  256>>>(Whh,           (float*)pWhhT,          G4, Hh);
    transpose_tiled<<<dim3(16, 64),  256>>>(Whh + G4*Hh,   (float*)pWhhT + Hh*G4,  G4, Hh);
    transpose_tiled<<<dim3(16, 16),  256>>>(Wq,    (float*)pWqT,    Hh, Hh);
    transpose_tiled<<<dim3(32, 16),  256>>>(hattW, (float*)pHattWT, Hh, 2*Hh);

    init_kernel<<<(Bz*Hh + 255)/256, 256>>>(pooled, embed, sos);
    kv_kernel<<<(Bz*Hh*Ss + 255)/256, 256>>>(img, Wk, bk, Wv, bv);
    t0_kernel<<<(Vv + 255)/256, 256>>>(projb, res);

    loop_kernel<<<NBLK, 256, SMEM_BYTES>>>(bih, bhh, projb, bq, hattb, embed, res);
}

// round 5
// speedup vs baseline: 1.0770x; 1.0770x over previous
#include <cuda_runtime.h>
#include <math.h>

#define Bz 32
#define Hh 512
#define Vv 10000
#define Tt 20
#define Ss 49
#define G4 2048
#define NBLK 148
#define NTILES 313
#define SM_FLOATS (32*1024 + 32*32 + 64)
#define SMEM_BYTES (SM_FLOATS * 4)

// ---------------- device scratch ----------------
__device__ float g_keysT[Bz*Ss*Hh];      // [b][s][d]
__device__ float g_valsSD[Bz*Ss*Hh];     // [b][s][d]  (values, coalesced layout)
__device__ float g_h[2*Bz*Hh];           // post-cell hidden
__device__ float g_hF[2*Bz*Hh];          // post-attention hidden
__device__ float g_c[2*Bz*Hh];
__device__ float g_emb[Bz*Hh];
__device__ float g_q[2*Bz*Hh];
__device__ float g_attn[2*Bz*Hh];
__device__ float g_pmax[NTILES*Bz];
__device__ int   g_pidx[NTILES*Bz];
__device__ int   g_tok[Bz];
__device__ float g_Wg[2*1024*G4];        // [l][k(1024: ih|hh)][gi*4+gate]
__device__ float g_projWT[Hh*Vv];        // [d][v]
__device__ float g_WqT[Hh*Hh];           // [k][d]
__device__ float g_hattWT[2*Hh*Hh];      // [k(1024)][d]
__device__ unsigned g_bar_count = 0;
__device__ volatile unsigned g_bar_gen = 0;

__device__ __forceinline__ float sigm(float x) { return 1.0f / (1.0f + expf(-x)); }

// ---------------- grid barrier ----------------
__device__ __forceinline__ void gsync() {
    __syncthreads();
    if (threadIdx.x == 0) {
        unsigned gen = g_bar_gen;
        __threadfence();
        unsigned t = atomicAdd(&g_bar_count, 1u);
        if (t == NBLK - 1) {
            g_bar_count = 0u;
            __threadfence();
            g_bar_gen = gen + 1u;
        } else {
            while (g_bar_gen == gen) {
                unsigned ns = 40;
                asm volatile("nanosleep.u32 %0;" :: "r"(ns));
            }
        }
        __threadfence();
    }
    __syncthreads();
}

// ---------------- gates + cell, one layer (blocks 0..63) ----------------
__device__ void phase_gates(int l, float* S, const float* __restrict__ bih,
                            const float* __restrict__ bhh) {
    int tid = threadIdx.x, blk = blockIdx.x;
    float* sX = S;                  // [32][1024]  (x | h_rec)
    float* sg = S + 32*1024;        // [32 cols][32 b]
    const float4* x4 = (const float4*)((l == 0) ? g_emb : g_h);
    const float4* h4 = (const float4*)(g_hF + l*Bz*Hh);
    float4* d4 = (float4*)sX;
    for (int i = tid; i < 32*128; i += 256) {
        int b = i >> 7, kq = i & 127;
        d4[b*256 + kq]       = x4[i];
        d4[b*256 + 128 + kq] = h4[i];
    }
    __syncthreads();

    int lane = tid & 31, bg = tid >> 5;
    const float* W = g_Wg + l*(1024*G4) + blk*32 + lane;
    const float* a0 = &sX[(bg*4 + 0)*1024];
    const float* a1 = &sX[(bg*4 + 1)*1024];
    const float* a2 = &sX[(bg*4 + 2)*1024];
    const float* a3 = &sX[(bg*4 + 3)*1024];
    float acc0 = 0.f, acc1 = 0.f, acc2 = 0.f, acc3 = 0.f;
#pragma unroll 4
    for (int k = 0; k < 1024; k += 4) {
        const float* wp = W + k*G4;
        float w0 = wp[0], w1 = wp[G4], w2 = wp[2*G4], w3 = wp[3*G4];
        float4 v0 = *(const float4*)&a0[k];
        float4 v1 = *(const float4*)&a1[k];
        float4 v2 = *(const float4*)&a2[k];
        float4 v3 = *(const float4*)&a3[k];
        acc0 += v0.x*w0 + v0.y*w1 + v0.z*w2 + v0.w*w3;
        acc1 += v1.x*w0 + v1.y*w1 + v1.z*w2 + v1.w*w3;
        acc2 += v2.x*w0 + v2.y*w1 + v2.z*w2 + v2.w*w3;
        acc3 += v3.x*w0 + v3.y*w1 + v3.z*w2 + v3.w*w3;
    }
    sg[lane*32 + bg*4 + 0] = acc0;
    sg[lane*32 + bg*4 + 1] = acc1;
    sg[lane*32 + bg*4 + 2] = acc2;
    sg[lane*32 + bg*4 + 3] = acc3;
    __syncthreads();

    // cell: 8 gi x 32 b
    int gi_l = tid >> 5, b = tid & 31;
    int gi = blk*8 + gi_l;
    const float* bi = bih + l*G4; const float* bh = bhh + l*G4;
    float vi = sg[(gi_l*4 + 0)*32 + b] + bi[gi]        + bh[gi];
    float vf = sg[(gi_l*4 + 1)*32 + b] + bi[512 + gi]  + bh[512 + gi];
    float vg = sg[(gi_l*4 + 2)*32 + b] + bi[1024 + gi] + bh[1024 + gi];
    float vo = sg[(gi_l*4 + 3)*32 + b] + bi[1536 + gi] + bh[1536 + gi];
    int idx = (l*Bz + b)*Hh + gi;
    float c  = g_c[idx];
    float cn = sigm(vf)*c + sigm(vi)*tanhf(vg);
    g_c[idx] = cn;
    g_h[idx] = sigm(vo)*tanhf(cn);
}

// ---------------- batched q-GEMM: 16 blocks x 32 d-cols ----------------
__device__ void phase_q(int l, int qb, float* S, const float* __restrict__ bq) {
    int tid = threadIdx.x;
    float* sH = S;
    const float4* h4 = (const float4*)(g_h + l*Bz*Hh);
    float4* s4 = (float4*)sH;
    for (int i = tid; i < Bz*Hh/4; i += 256) s4[i] = h4[i];
    __syncthreads();

    int lane = tid & 31, bg = tid >> 5;
    int d = qb*32 + lane;
    float acc0 = 0.f, acc1 = 0.f, acc2 = 0.f, acc3 = 0.f;
    const float* a0 = &sH[(bg*4 + 0)*Hh];
    const float* a1 = &sH[(bg*4 + 1)*Hh];
    const float* a2 = &sH[(bg*4 + 2)*Hh];
    const float* a3 = &sH[(bg*4 + 3)*Hh];
#pragma unroll 4
    for (int k = 0; k < Hh; k += 4) {
        const float* wp = &g_WqT[k*Hh + d];
        float w0 = wp[0], w1 = wp[Hh], w2 = wp[2*Hh], w3 = wp[3*Hh];
        float4 v0 = *(const float4*)&a0[k];
        float4 v1 = *(const float4*)&a1[k];
        float4 v2 = *(const float4*)&a2[k];
        float4 v3 = *(const float4*)&a3[k];
        acc0 += v0.x*w0 + v0.y*w1 + v0.z*w2 + v0.w*w3;
        acc1 += v1.x*w0 + v1.y*w1 + v1.z*w2 + v1.w*w3;
        acc2 += v2.x*w0 + v2.y*w1 + v2.z*w2 + v2.w*w3;
        acc3 += v3.x*w0 + v3.y*w1 + v3.z*w2 + v3.w*w3;
    }
    float bv = bq[d];
    g_q[(l*Bz + bg*4 + 0)*Hh + d] = tanhf(acc0 + bv);
    g_q[(l*Bz + bg*4 + 1)*Hh + d] = tanhf(acc1 + bv);
    g_q[(l*Bz + bg*4 + 2)*Hh + d] = tanhf(acc2 + bv);
    g_q[(l*Bz + bg*4 + 3)*Hh + d] = tanhf(acc3 + bv);
}

// ---------------- scores + softmax + attn vector for 2 batches ----------------
__device__ void phase_att(int l, int b0, float* S) {
    int tid = threadIdx.x;
    float* sq   = S;            // [2][512]
    float* ssc  = S + 1024;     // [2][64]
    float* sw   = S + 1152;     // [2][64]
    float* smax = S + 1280;     // [2]
    float* sinv = S + 1284;     // [2]
    for (int i = tid; i < 2*Hh; i += 256) {
        int bb = i >> 9;
        sq[i] = g_q[(l*Bz + b0 + bb)*Hh + (i & 511)];
    }
    __syncthreads();

    int warp = tid >> 5, lane = tid & 31;
    int half = warp >> 2, w2 = warp & 3;
    int b = b0 + half;
    for (int s = w2; s < Ss; s += 4) {
        const float* kp = &g_keysT[(b*Ss + s)*Hh];
        const float* qp = &sq[half*Hh];
        float p = 0.f;
        for (int d = lane; d < Hh; d += 32) p += qp[d]*kp[d];
#pragma unroll
        for (int o = 16; o; o >>= 1) p += __shfl_xor_sync(0xffffffffu, p, o);
        if (lane == 0) ssc[half*64 + s] = p * (1.0f/7.0f);
    }
    __syncthreads();
    if (tid < 2) {
        float mx = -INFINITY;
        for (int s = 0; s < Ss; s++) mx = fmaxf(mx, ssc[tid*64 + s]);
        smax[tid] = mx;
    }
    __syncthreads();
    if (tid < 128) {
        int bb = tid >> 6, s = tid & 63;
        if (s < Ss) sw[bb*64 + s] = expf(ssc[bb*64 + s] - smax[bb]);
    }
    __syncthreads();
    if (tid < 2) {
        float sum = 0.f;
        for (int s = 0; s < Ss; s++) sum += sw[tid*64 + s];
        sinv[tid] = 1.0f / sum;
    }
    __syncthreads();
#pragma unroll
    for (int rep = 0; rep < 4; rep++) {
        int idx = rep*256 + tid;
        int bb = idx >> 9, d = idx & 511;
        const float* wv = &sw[bb*64];
        float a = 0.f;
#pragma unroll
        for (int s = 0; s < Ss; s++)
            a += wv[s] * g_valsSD[((b0 + bb)*Ss + s)*Hh + d];
        g_attn[(l*Bz + b0 + bb)*Hh + d] = a * sinv[bb];
    }
}

// ---------------- hatt GEMM: 64 blocks = 16 d-groups x 4 b-quads(8b) ----------------
__device__ void phase_hatt(int l, float* S, const float* __restrict__ hattb) {
    int tid = threadIdx.x, blk = blockIdx.x;
    int dg = blk >> 2, bq4 = blk & 3;
    int b0 = bq4*8;
    float* sX = S;               // [8][1024]  (attn | h)
    float* sred = S + 8*1024;    // [256][8]
    for (int i = tid; i < 8*1024; i += 256) {
        int b = i >> 10, kk = i & 1023;
        float v = (kk < 512) ? g_attn[(l*Bz + b0 + b)*Hh + kk]
                             : g_h[(l*Bz + b0 + b)*Hh + (kk - 512)];
        sX[i] = v;
    }
    __syncthreads();

    int lane = tid & 31, w = tid >> 5;
    int d = dg*32 + lane;
    float acc[8];
#pragma unroll
    for (int j = 0; j < 8; j++) acc[j] = 0.f;
    int k0 = w*128;
#pragma unroll 2
    for (int kk = k0; kk < k0 + 128; kk += 4) {
        const float* wp = &g_hattWT[kk*Hh + d];
        float w0 = wp[0], w1 = wp[Hh], w2 = wp[2*Hh], w3 = wp[3*Hh];
#pragma unroll
        for (int j = 0; j < 8; j++) {
            float4 a = *(const float4*)&sX[j*1024 + kk];
            acc[j] += a.x*w0 + a.y*w1 + a.z*w2 + a.w*w3;
        }
    }
#pragma unroll
    for (int j = 0; j < 8; j++) sred[(w*32 + lane)*8 + j] = acc[j];
    __syncthreads();

    int d_l = tid >> 3, j = tid & 7;
    float s = 0.f;
#pragma unroll
    for (int w2 = 0; w2 < 8; w2++) s += sred[(w2*32 + d_l)*8 + j];
    int dd = dg*32 + d_l;
    g_hF[(l*Bz + b0 + j)*Hh + dd] = tanhf(s + hattb[dd]);
}

// ---------------- logits tile: 32 v x 32 b + argmax partials ----------------
__device__ void logit_tile(const float* __restrict__ sH, int tile, int t,
                           const float* __restrict__ projb, float* __restrict__ res) {
    int tid = threadIdx.x;
    int vl = tid & 31, bg = tid >> 5;
    int v  = tile*32 + vl;
    int vc = (v < Vv) ? v : (Vv - 1);
    float acc0 = 0.f, acc1 = 0.f, acc2 = 0.f, acc3 = 0.f;
    const float* h0 = &sH[(bg*4 + 0)*Hh];
    const float* h1 = &sH[(bg*4 + 1)*Hh];
    const float* h2 = &sH[(bg*4 + 2)*Hh];
    const float* h3 = &sH[(bg*4 + 3)*Hh];
#pragma unroll 2
    for (int d = 0; d < Hh; d += 4) {
        const float* wp = &g_projWT[d*Vv + vc];
        float w0 = wp[0], w1 = wp[Vv], w2 = wp[2*Vv], w3 = wp[3*Vv];
        float4 a0 = *(const float4*)&h0[d];
        float4 a1 = *(const float4*)&h1[d];
        float4 a2 = *(const float4*)&h2[d];
        float4 a3 = *(const float4*)&h3[d];
        acc0 += a0.x*w0 + a0.y*w1 + a0.z*w2 + a0.w*w3;
        acc1 += a1.x*w0 + a1.y*w1 + a1.z*w2 + a1.w*w3;
        acc2 += a2.x*w0 + a2.y*w1 + a2.z*w2 + a2.w*w3;
        acc3 += a3.x*w0 + a3.y*w1 + a3.z*w2 + a3.w*w3;
    }
    float pb = projb[vc];
    bool valid = (v < Vv);
    float a[4] = {acc0, acc1, acc2, acc3};
#pragma unroll
    for (int i = 0; i < 4; i++) {
        int b = bg*4 + i;
        float r = a[i] + pb;
        if (valid) res[b*(Vv*Tt) + v*Tt + t] = r;
        float mv = valid ? r : -INFINITY;
        int   mi = v;
#pragma unroll
        for (int o = 16; o; o >>= 1) {
            float ov = __shfl_xor_sync(0xffffffffu, mv, o);
            int   oi = __shfl_xor_sync(0xffffffffu, mi, o);
            if (ov > mv || (ov == mv && oi < mi)) { mv = ov; mi = oi; }
        }
        if (vl == 0) { g_pmax[tile*32 + b] = mv; g_pidx[tile*32 + b] = mi; }
    }
}

__device__ void phase_logits(float* S, const float* __restrict__ projb,
                             float* __restrict__ res, int t) {
    int tid = threadIdx.x, blk = blockIdx.x;
    const float4* H4 = (const float4*)(g_h + Bz*Hh);
    float4* S4 = (float4*)S;
    for (int i = tid; i < Bz*Hh/4; i += 256) S4[i] = H4[i];
    __syncthreads();
    logit_tile(S, blk,       t, projb, res);
    logit_tile(S, blk + 116, t, projb, res);
    if (blk < 81) logit_tile(S, blk + 232, t, projb, res);
}

// ---------------- argmax finalize + embedding gather ----------------
__device__ void phase_argmax(float* S, const float* __restrict__ embed) {
    int tid = threadIdx.x;
    float* sv = S;
    int* si = (int*)(S + 256);
    int b = tid & 31, j = tid >> 5;
    float mv = -INFINITY; int mi = 0;
    for (int tl = j; tl < NTILES; tl += 8) {
        float v = g_pmax[tl*32 + b]; int ix = g_pidx[tl*32 + b];
        if (v > mv || (v == mv && ix < mi)) { mv = v; mi = ix; }
    }
    sv[j*32 + b] = mv; si[j*32 + b] = mi;
    __syncthreads();
    if (tid < 32) {
        float bv = sv[b]; int bi = si[b];
        for (int j2 = 1; j2 < 8; j2++) {
            float v = sv[j2*32 + b]; int ix = si[j2*32 + b];
            if (v > bv || (v == bv && ix < bi)) { bv = v; bi = ix; }
        }
        g_tok[b] = bi;
    }
    __syncthreads();
    for (int i = tid; i < Bz*Hh; i += 256) {
        int bb = i >> 9, d = i & 511;
        g_emb[i] = embed[g_tok[bb]*Hh + d];
    }
}

// ---------------- persistent loop kernel ----------------
__global__ __launch_bounds__(256, 1)
void loop_kernel(const float* __restrict__ bih, const float* __restrict__ bhh,
                 const float* __restrict__ projb, const float* __restrict__ bq,
                 const float* __restrict__ hattb, const float* __restrict__ embed,
                 float* __restrict__ res) {
    extern __shared__ float S[];
    int blk = blockIdx.x;
    for (int t = 0; t < Tt - 1; t++) {
        // Phase 1: layer-0 LSTM
        if (blk < 64) phase_gates(0, S, bih, bhh);
        gsync();
        // Phase 2: layer-1 LSTM || q0
        if (blk < 64) phase_gates(1, S, bih, bhh);
        else if (blk < 80) phase_q(0, blk - 64, S, bq);
        gsync();
        // Phase 3: logits || att0 softmax-V || q1
        if (blk < 116) phase_logits(S, projb, res, t + 1);
        else if (blk < 132) phase_att(0, (blk - 116)*2, S);
        else phase_q(1, blk - 132, S, bq);
        gsync();
        // Phase 4: hatt0 || att1 softmax-V || argmax+emb
        if (blk < 64) phase_hatt(0, S, hattb);
        else if (blk < 80) phase_att(1, (blk - 64)*2, S);
        else if (blk == 80) phase_argmax(S, embed);
        gsync();
        // Phase 5: hatt1
        if (blk < 64) phase_hatt(1, S, hattb);
        gsync();
    }
}

// ---------------- prep kernels ----------------
__global__ void transpose_tiled(const float* __restrict__ src, float* __restrict__ dst,
                                int R, int C) {
    __shared__ float tile[32][33];
    int tx = threadIdx.x & 31, ty = threadIdx.x >> 5;
    int bx = blockIdx.x * 32, by = blockIdx.y * 32;
    for (int i = 0; i < 32; i += 8) {
        int r = by + ty + i, c = bx + tx;
        if (r < R && c < C) tile[ty + i][tx] = src[r*C + c];
    }
    __syncthreads();
    for (int i = 0; i < 32; i += 8) {
        int r = by + tx, c = bx + ty + i;
        if (r < R && c < C) dst[c*R + r] = tile[tx][ty + i];
    }
}

// Reorder gate weights: g_Wg[l][k(0..1023)][gi*4+g] where k<512 -> Wih, else Whh
__global__ void gates_reorder(const float* __restrict__ Wih, const float* __restrict__ Whh) {
    int id = blockIdx.x * 256 + threadIdx.x;   // 2*1024*2048 total
    int c = id & 2047;
    int k = (id >> 11) & 1023;
    int l = id >> 21;
    int gi = c >> 2, g = c & 3;
    int row = l*G4 + g*512 + gi;
    float v = (k < 512) ? Wih[row*512 + k] : Whh[row*512 + (k - 512)];
    g_Wg[id] = v;
}

__global__ void init_kernel(const float* __restrict__ pooled,
                            const float* __restrict__ embed,
                            const int* __restrict__ sos) {
    int i = blockIdx.x * 256 + threadIdx.x;
    if (i >= Bz * Hh) return;
    int d = i & (Hh - 1);
    g_emb[i] = embed[sos[0]*Hh + d];
    float p = pooled[i];
    g_hF[i] = p; g_hF[Bz*Hh + i] = p;
    g_c[i]  = p; g_c[Bz*Hh + i]  = p;
}

__global__ void kv_kernel(const float* __restrict__ chan,
                          const float* __restrict__ Wk, const float* __restrict__ bk,
                          const float* __restrict__ Wv, const float* __restrict__ bv) {
    int id = blockIdx.x * 256 + threadIdx.x;
    if (id >= Bz * Ss * Hh) return;
    int d = id & 511;
    int r = id >> 9;
    int s = r % Ss;
    int b = r / Ss;
    const float* cp  = &chan[(b*Hh + d)*Ss];
    const float* wkp = &Wk[s*Ss];
    const float* wvp = &Wv[s*Ss];
    float aK = bk[s], aV = bv[s];
#pragma unroll
    for (int k = 0; k < Ss; k++) { float c = cp[k]; aK += c*wkp[k]; aV += c*wvp[k]; }
    g_keysT[(b*Ss + s)*Hh + d]  = tanhf(aK);
    g_valsSD[(b*Ss + s)*Hh + d] = tanhf(aV);
}

__global__ void t0_kernel(const float* __restrict__ projb, float* __restrict__ res) {
    int v = blockIdx.x * 256 + threadIdx.x;
    if (v >= Vv) return;
    float acc = projb[v];
    for (int d = 0; d < Hh; d++) acc += g_emb[d] * g_projWT[d*Vv + v];
    for (int b = 0; b < Bz; b++) res[b*(Vv*Tt) + v*Tt] = acc;
}

// ---------------- host launcher ----------------
extern "C" void kernel_launch(void* const* d_in, const int* in_sizes, int n_in,
                              void* d_out, int out_size) {
    const float* img    = (const float*)d_in[0];
    const float* pooled = (const float*)d_in[1];
    const float* embed  = (const float*)d_in[2];
    const float* Wq     = (const float*)d_in[3];
    const float* bq     = (const float*)d_in[4];
    const float* Wk     = (const float*)d_in[5];
    const float* bk     = (const float*)d_in[6];
    const float* Wv     = (const float*)d_in[7];
    const float* bv     = (const float*)d_in[8];
    const float* Wih    = (const float*)d_in[9];
    const float* Whh    = (const float*)d_in[10];
    const float* bih    = (const float*)d_in[11];
    const float* bhh    = (const float*)d_in[12];
    const float* projW  = (const float*)d_in[13];
    const float* projb  = (const float*)d_in[14];
    const float* hattW  = (const float*)d_in[15];
    const float* hattb  = (const float*)d_in[16];
    const int*   sos    = (const int*)d_in[17];
    float* res = (float*)d_out;

    void *pProjWT, *pWqT, *pHattWT;
    cudaGetSymbolAddress(&pProjWT, g_projWT);
    cudaGetSymbolAddress(&pWqT,    g_WqT);
    cudaGetSymbolAddress(&pHattWT, g_hattWT);

    cudaFuncSetAttribute(loop_kernel, cudaFuncAttributeMaxDynamicSharedMemorySize, SMEM_BYTES);

    transpose_tiled<<<dim3(16, 313), 256>>>(projW, (float*)pProjWT, Vv, Hh);
    transpose_tiled<<<dim3(16, 16),  256>>>(Wq,    (float*)pWqT,    Hh, Hh);
    transpose_tiled<<<dim3(32, 16),  256>>>(hattW, (float*)pHattWT, Hh, 2*Hh);
    gates_reorder<<<(2*1024*G4)/256, 256>>>(Wih, Whh);

    init_kernel<<<(Bz*Hh + 255)/256, 256>>>(pooled, embed, sos);
    kv_kernel<<<(Bz*Ss*Hh + 255)/256, 256>>>(img, Wk, bk, Wv, bv);
    t0_kernel<<<(Vv + 255)/256, 256>>>(projb, res);

    loop_kernel<<<NBLK, 256, SMEM_BYTES>>>(bih, bhh, projb, bq, hattb, embed, res);
}

// round 8
// speedup vs baseline: 1.1905x; 1.1053x over previous
#include <cuda_runtime.h>
#include <math.h>

#define Bz 32
#define Hh 512
#define Vv 10000
#define Tt 20
#define Ss 49
#define G4 2048
#define NBLK 148
#define NTILES 313
#define SM_FLOATS (32*1024 + 32*32 + 64)
#define SMEM_BYTES (SM_FLOATS * 4)

// ---------------- device scratch ----------------
__device__ float g_keysT[Bz*Ss*Hh];      // [b][s][d]
__device__ float g_valsSD[Bz*Ss*Hh];     // [b][s][d]
__device__ float g_h[2*Bz*Hh];           // post-cell hidden
__device__ float g_hF[2*Bz*Hh];          // post-attention hidden
__device__ float g_c[2*Bz*Hh];
__device__ float g_emb[Bz*Hh];
__device__ float g_q[2*Bz*Hh];
__device__ float g_attn[2*Bz*Hh];
__device__ float g_pmax[NTILES*Bz];
__device__ int   g_pidx[NTILES*Bz];
__device__ int   g_tok[Bz];
__device__ float g_Wg[2*1024*G4];        // [l][k(1024: ih|hh)][gi*4+gate]
__device__ float g_projWT[Hh*Vv + 64];   // [d][v] (+pad for OOB-safe prefetch)
__device__ float g_WqT[Hh*Hh];           // [k][d]
__device__ float g_hattWT[2*Hh*Hh];      // [k(1024)][d]
__device__ unsigned g_bar_count;         // zero-init
__device__ unsigned g_bar_gen;           // zero-init, monotonic across replays

__device__ __forceinline__ float sigm(float x) { return 1.0f / (1.0f + expf(-x)); }

// ---------------- grid barrier (release arrive / acquire spin / L1 inval) ----------------
__device__ __forceinline__ unsigned ld_acquire_gpu(unsigned* p) {
    unsigned v;
    asm volatile("ld.acquire.gpu.global.u32 %0, [%1];" : "=r"(v) : "l"(p) : "memory");
    return v;
}
__device__ __forceinline__ void gsync(unsigned &mygen) {
    __syncthreads();
    mygen++;
    if (threadIdx.x == 0) {
        unsigned old;
        asm volatile("atom.release.gpu.global.add.u32 %0, [%1], %2;"
                     : "=r"(old) : "l"(&g_bar_count), "r"(1u) : "memory");
        if (old == NBLK - 1) {
            asm volatile("st.relaxed.gpu.global.u32 [%0], %1;"
                         :: "l"(&g_bar_count), "r"(0u) : "memory");
            asm volatile("st.release.gpu.global.u32 [%0], %1;"
                         :: "l"(&g_bar_gen), "r"(mygen) : "memory");
        } else {
            while (ld_acquire_gpu(&g_bar_gen) < mygen) {
                asm volatile("nanosleep.u32 32;");
            }
        }
        __threadfence();   // CCTL.IVALL — invalidate L1D so weak loads see peers' writes
    }
    __syncthreads();
}

// ---------------- gates + cell, one layer (blocks 0..63) ----------------
__device__ void phase_gates(int l, float* S, const float* __restrict__ bih,
                            const float* __restrict__ bhh) {
    int tid = threadIdx.x, blk = blockIdx.x;
    float* sX = S;                  // [32][1024]  (x | h_rec)
    float* sg = S + 32*1024;        // [32 cols][32 b]
    const float4* x4 = (const float4*)((l == 0) ? g_emb : g_h);
    const float4* h4 = (const float4*)(g_hF + l*Bz*Hh);
    float4* d4 = (float4*)sX;
    for (int i = tid; i < 32*128; i += 256) {
        int b = i >> 7, kq = i & 127;
        d4[b*256 + kq]       = x4[i];
        d4[b*256 + 128 + kq] = h4[i];
    }
    __syncthreads();

    int lane = tid & 31, bg = tid >> 5;
    const float* W = g_Wg + l*(1024*G4) + blk*32 + lane;
    const float* a0 = &sX[(bg*4 + 0)*1024];
    const float* a1 = &sX[(bg*4 + 1)*1024];
    const float* a2 = &sX[(bg*4 + 2)*1024];
    const float* a3 = &sX[(bg*4 + 3)*1024];
    float acc0 = 0.f, acc1 = 0.f, acc2 = 0.f, acc3 = 0.f;
#pragma unroll 4
    for (int k = 0; k < 1024; k += 4) {
        const float* wp = W + k*G4;
        float w0 = wp[0], w1 = wp[G4], w2 = wp[2*G4], w3 = wp[3*G4];
        float4 v0 = *(const float4*)&a0[k];
        float4 v1 = *(const float4*)&a1[k];
        float4 v2 = *(const float4*)&a2[k];
        float4 v3 = *(const float4*)&a3[k];
        acc0 += v0.x*w0 + v0.y*w1 + v0.z*w2 + v0.w*w3;
        acc1 += v1.x*w0 + v1.y*w1 + v1.z*w2 + v1.w*w3;
        acc2 += v2.x*w0 + v2.y*w1 + v2.z*w2 + v2.w*w3;
        acc3 += v3.x*w0 + v3.y*w1 + v3.z*w2 + v3.w*w3;
    }
    sg[lane*32 + bg*4 + 0] = acc0;
    sg[lane*32 + bg*4 + 1] = acc1;
    sg[lane*32 + bg*4 + 2] = acc2;
    sg[lane*32 + bg*4 + 3] = acc3;
    __syncthreads();

    int gi_l = tid >> 5, b = tid & 31;
    int gi = blk*8 + gi_l;
    const float* bi = bih + l*G4; const float* bh = bhh + l*G4;
    float vi = sg[(gi_l*4 + 0)*32 + b] + bi[gi]        + bh[gi];
    float vf = sg[(gi_l*4 + 1)*32 + b] + bi[512 + gi]  + bh[512 + gi];
    float vg = sg[(gi_l*4 + 2)*32 + b] + bi[1024 + gi] + bh[1024 + gi];
    float vo = sg[(gi_l*4 + 3)*32 + b] + bi[1536 + gi] + bh[1536 + gi];
    int idx = (l*Bz + b)*Hh + gi;
    float c  = g_c[idx];
    float cn = sigm(vf)*c + sigm(vi)*tanhf(vg);
    g_c[idx] = cn;
    g_h[idx] = sigm(vo)*tanhf(cn);
}

// ---------------- batched q-GEMM: 16 blocks x 32 d-cols ----------------
__device__ void phase_q(int l, int qb, float* S, const float* __restrict__ bq) {
    int tid = threadIdx.x;
    float* sH = S;
    const float4* h4 = (const float4*)(g_h + l*Bz*Hh);
    float4* s4 = (float4*)sH;
    for (int i = tid; i < Bz*Hh/4; i += 256) s4[i] = h4[i];
    __syncthreads();

    int lane = tid & 31, bg = tid >> 5;
    int d = qb*32 + lane;
    float acc0 = 0.f, acc1 = 0.f, acc2 = 0.f, acc3 = 0.f;
    const float* a0 = &sH[(bg*4 + 0)*Hh];
    const float* a1 = &sH[(bg*4 + 1)*Hh];
    const float* a2 = &sH[(bg*4 + 2)*Hh];
    const float* a3 = &sH[(bg*4 + 3)*Hh];
#pragma unroll 4
    for (int k = 0; k < Hh; k += 4) {
        const float* wp = &g_WqT[k*Hh + d];
        float w0 = wp[0], w1 = wp[Hh], w2 = wp[2*Hh], w3 = wp[3*Hh];
        float4 v0 = *(const float4*)&a0[k];
        float4 v1 = *(const float4*)&a1[k];
        float4 v2 = *(const float4*)&a2[k];
        float4 v3 = *(const float4*)&a3[k];
        acc0 += v0.x*w0 + v0.y*w1 + v0.z*w2 + v0.w*w3;
        acc1 += v1.x*w0 + v1.y*w1 + v1.z*w2 + v1.w*w3;
        acc2 += v2.x*w0 + v2.y*w1 + v2.z*w2 + v2.w*w3;
        acc3 += v3.x*w0 + v3.y*w1 + v3.z*w2 + v3.w*w3;
    }
    float bv = bq[d];
    g_q[(l*Bz + bg*4 + 0)*Hh + d] = tanhf(acc0 + bv);
    g_q[(l*Bz + bg*4 + 1)*Hh + d] = tanhf(acc1 + bv);
    g_q[(l*Bz + bg*4 + 2)*Hh + d] = tanhf(acc2 + bv);
    g_q[(l*Bz + bg*4 + 3)*Hh + d] = tanhf(acc3 + bv);
}

// ---------------- scores + softmax + attn vector for 2 batches ----------------
__device__ void phase_att(int l, int b0, float* S) {
    int tid = threadIdx.x;
    float* sq   = S;            // [2][512]
    float* ssc  = S + 1024;
    float* sw   = S + 1152;
    float* smax = S + 1280;
    float* sinv = S + 1284;
    for (int i = tid; i < 2*Hh; i += 256) {
        int bb = i >> 9;
        sq[i] = g_q[(l*Bz + b0 + bb)*Hh + (i & 511)];
    }
    __syncthreads();

    int warp = tid >> 5, lane = tid & 31;
    int half = warp >> 2, w2 = warp & 3;
    int b = b0 + half;
    for (int s = w2; s < Ss; s += 4) {
        const float* kp = &g_keysT[(b*Ss + s)*Hh];
        const float* qp = &sq[half*Hh];
        float p = 0.f;
        for (int d = lane; d < Hh; d += 32) p += qp[d]*kp[d];
#pragma unroll
        for (int o = 16; o; o >>= 1) p += __shfl_xor_sync(0xffffffffu, p, o);
        if (lane == 0) ssc[half*64 + s] = p * (1.0f/7.0f);
    }
    __syncthreads();
    if (tid < 2) {
        float mx = -INFINITY;
        for (int s = 0; s < Ss; s++) mx = fmaxf(mx, ssc[tid*64 + s]);
        smax[tid] = mx;
    }
    __syncthreads();
    if (tid < 128) {
        int bb = tid >> 6, s = tid & 63;
        if (s < Ss) sw[bb*64 + s] = expf(ssc[bb*64 + s] - smax[bb]);
    }
    __syncthreads();
    if (tid < 2) {
        float sum = 0.f;
        for (int s = 0; s < Ss; s++) sum += sw[tid*64 + s];
        sinv[tid] = 1.0f / sum;
    }
    __syncthreads();
#pragma unroll
    for (int rep = 0; rep < 4; rep++) {
        int idx = rep*256 + tid;
        int bb = idx >> 9, d = idx & 511;
        const float* wv = &sw[bb*64];
        float a = 0.f;
#pragma unroll
        for (int s = 0; s < Ss; s++)
            a += wv[s] * g_valsSD[((b0 + bb)*Ss + s)*Hh + d];
        g_attn[(l*Bz + b0 + bb)*Hh + d] = a * sinv[bb];
    }
}

// ---------------- hatt GEMM: 64 blocks = 16 d-groups x 4 b-quads(8b) ----------------
__device__ void phase_hatt(int l, float* S, const float* __restrict__ hattb) {
    int tid = threadIdx.x, blk = blockIdx.x;
    int dg = blk >> 2, bq4 = blk & 3;
    int b0 = bq4*8;
    float* sX = S;               // [8][1024]
    float* sred = S + 8*1024;    // [256][8]
    for (int i = tid; i < 8*1024; i += 256) {
        int b = i >> 10, kk = i & 1023;
        float v = (kk < 512) ? g_attn[(l*Bz + b0 + b)*Hh + kk]
                             : g_h[(l*Bz + b0 + b)*Hh + (kk - 512)];
        sX[i] = v;
    }
    __syncthreads();

    int lane = tid & 31, w = tid >> 5;
    int d = dg*32 + lane;
    float acc[8];
#pragma unroll
    for (int j = 0; j < 8; j++) acc[j] = 0.f;
    int k0 = w*128;
#pragma unroll 2
    for (int kk = k0; kk < k0 + 128; kk += 4) {
        const float* wp = &g_hattWT[kk*Hh + d];
        float w0 = wp[0], w1 = wp[Hh], w2 = wp[2*Hh], w3 = wp[3*Hh];
#pragma unroll
        for (int j = 0; j < 8; j++) {
            float4 a = *(const float4*)&sX[j*1024 + kk];
            acc[j] += a.x*w0 + a.y*w1 + a.z*w2 + a.w*w3;
        }
    }
#pragma unroll
    for (int j = 0; j < 8; j++) sred[(w*32 + lane)*8 + j] = acc[j];
    __syncthreads();

    int d_l = tid >> 3, j = tid & 7;
    float s = 0.f;
#pragma unroll
    for (int w2 = 0; w2 < 8; w2++) s += sred[(w2*32 + d_l)*8 + j];
    int dd = dg*32 + d_l;
    g_hF[(l*Bz + b0 + j)*Hh + dd] = tanhf(s + hattb[dd]);
}

// ---------------- logits tile with smem-buffered W (32 v x 32 b) ----------------
__device__ void logit_tile_smem(const float* __restrict__ sH, float* __restrict__ sW,
                                int tile, int t,
                                const float* __restrict__ projb, float* __restrict__ res) {
    int tid = threadIdx.x;
    int vl = tid & 31, bg = tid >> 5;
    int v  = tile*32 + vl;
    int v0 = tile*32;
    bool valid = (v < Vv);

    int f0 = tid, f1 = tid + 256;
    int row0 = f0 >> 3, q0 = (f0 & 7)*4;
    int row1 = f1 >> 3, q1 = (f1 & 7)*4;

    float4 r0 = *(const float4*)&g_projWT[row0*Vv + v0 + q0];
    float4 r1 = *(const float4*)&g_projWT[row1*Vv + v0 + q1];
    *(float4*)&sW[f0*4] = r0;
    *(float4*)&sW[f1*4] = r1;
    __syncthreads();

    float acc0 = 0.f, acc1 = 0.f, acc2 = 0.f, acc3 = 0.f;
    int buf = 0;
#pragma unroll
    for (int c = 0; c < 8; c++) {
        if (c < 7) {
            r0 = *(const float4*)&g_projWT[((c+1)*64 + row0)*Vv + v0 + q0];
            r1 = *(const float4*)&g_projWT[((c+1)*64 + row1)*Vv + v0 + q1];
        }
        const float* wc = sW + buf*2048;
        const float* h0 = &sH[(bg*4 + 0)*Hh + c*64];
        const float* h1 = &sH[(bg*4 + 1)*Hh + c*64];
        const float* h2 = &sH[(bg*4 + 2)*Hh + c*64];
        const float* h3 = &sH[(bg*4 + 3)*Hh + c*64];
#pragma unroll
        for (int dl = 0; dl < 64; dl += 4) {
            float w0 = wc[dl*32 + vl];
            float w1 = wc[(dl+1)*32 + vl];
            float w2 = wc[(dl+2)*32 + vl];
            float w3 = wc[(dl+3)*32 + vl];
            float4 a0 = *(const float4*)&h0[dl];
            float4 a1 = *(const float4*)&h1[dl];
            float4 a2 = *(const float4*)&h2[dl];
            float4 a3 = *(const float4*)&h3[dl];
            acc0 += a0.x*w0 + a0.y*w1 + a0.z*w2 + a0.w*w3;
            acc1 += a1.x*w0 + a1.y*w1 + a1.z*w2 + a1.w*w3;
            acc2 += a2.x*w0 + a2.y*w1 + a2.z*w2 + a2.w*w3;
            acc3 += a3.x*w0 + a3.y*w1 + a3.z*w2 + a3.w*w3;
        }
        if (c < 7) {
            int nb = buf ^ 1;
            *(float4*)&sW[nb*2048 + f0*4] = r0;
            *(float4*)&sW[nb*2048 + f1*4] = r1;
            __syncthreads();
            buf = nb;
        }
    }

    float pb = projb[valid ? v : (Vv - 1)];
    float a[4] = {acc0, acc1, acc2, acc3};
#pragma unroll
    for (int i = 0; i < 4; i++) {
        int b = bg*4 + i;
        float r = a[i] + pb;
        if (valid) res[b*(Vv*Tt) + v*Tt + t] = r;
        float mv = valid ? r : -INFINITY;
        int   mi = v;
#pragma unroll
        for (int o = 16; o; o >>= 1) {
            float ov = __shfl_xor_sync(0xffffffffu, mv, o);
            int   oi = __shfl_xor_sync(0xffffffffu, mi, o);
            if (ov > mv || (ov == mv && oi < mi)) { mv = ov; mi = oi; }
        }
        if (vl == 0) { g_pmax[tile*32 + b] = mv; g_pidx[tile*32 + b] = mi; }
    }
    __syncthreads();
}

// ---------------- phase 3: logits (all blocks) || q1 || att0 ----------------
__device__ void phase_logits3(float* S, const float* __restrict__ projb,
                              float* __restrict__ res, int t,
                              const float* __restrict__ bq) {
    int tid = threadIdx.x, blk = blockIdx.x;
    const float4* H4 = (const float4*)(g_h + Bz*Hh);
    float4* S4 = (float4*)S;
    for (int i = tid; i < Bz*Hh/4; i += 256) S4[i] = H4[i];
    __syncthreads();
    float* sW = S + 16384;
    logit_tile_smem(S, sW, blk*2,     t, projb, res);
    logit_tile_smem(S, sW, blk*2 + 1, t, projb, res);
    if (blk < 17) {
        logit_tile_smem(S, sW, 296 + blk, t, projb, res);
    } else if (blk < 33) {
        __syncthreads();
        phase_q(1, blk - 17, S, bq);
    } else if (blk < 49) {
        __syncthreads();
        phase_att(0, (blk - 33)*2, S);
    }
}

// ---------------- argmax finalize + embedding gather ----------------
__device__ void phase_argmax(float* S, const float* __restrict__ embed) {
    int tid = threadIdx.x;
    float* sv = S;
    int* si = (int*)(S + 256);
    int b = tid & 31, j = tid >> 5;
    float mv = -INFINITY; int mi = 0;
    for (int tl = j; tl < NTILES; tl += 8) {
        float v = g_pmax[tl*32 + b]; int ix = g_pidx[tl*32 + b];
        if (v > mv || (v == mv && ix < mi)) { mv = v; mi = ix; }
    }
    sv[j*32 + b] = mv; si[j*32 + b] = mi;
    __syncthreads();
    if (tid < 32) {
        float bv = sv[b]; int bi = si[b];
        for (int j2 = 1; j2 < 8; j2++) {
            float v = sv[j2*32 + b]; int ix = si[j2*32 + b];
            if (v > bv || (v == bv && ix < bi)) { bv = v; bi = ix; }
        }
        g_tok[b] = bi;
    }
    __syncthreads();
    for (int i = tid; i < Bz*Hh; i += 256) {
        int bb = i >> 9, d = i & 511;
        g_emb[i] = embed[g_tok[bb]*Hh + d];
    }
}

// ---------------- persistent loop kernel ----------------
__global__ __launch_bounds__(256, 1)
void loop_kernel(const float* __restrict__ bih, const float* __restrict__ bhh,
                 const float* __restrict__ projb, const float* __restrict__ bq,
                 const float* __restrict__ hattb, const float* __restrict__ embed,
                 float* __restrict__ res) {
    extern __shared__ float S[];
    int blk = blockIdx.x;
    unsigned mygen = 0;
    if (threadIdx.x == 0) {
        asm volatile("ld.relaxed.gpu.global.u32 %0, [%1];" : "=r"(mygen) : "l"(&g_bar_gen) : "memory");
    }
    for (int t = 0; t < Tt - 1; t++) {
        if (blk < 64) phase_gates(0, S, bih, bhh);
        gsync(mygen);
        if (blk < 64) phase_gates(1, S, bih, bhh);
        else if (blk < 80) phase_q(0, blk - 64, S, bq);
        gsync(mygen);
        phase_logits3(S, projb, res, t + 1, bq);
        gsync(mygen);
        if (blk < 64) phase_hatt(0, S, hattb);
        else if (blk < 80) phase_att(1, (blk - 64)*2, S);
        else if (blk == 80) phase_argmax(S, embed);
        gsync(mygen);
        if (blk < 64) phase_hatt(1, S, hattb);
        gsync(mygen);
    }
}

// ---------------- prep kernels (exactly 5 launches before loop) ----------------
__global__ void transpose_tiled(const float* __restrict__ src, float* __restrict__ dst,
                                int R, int C) {
    __shared__ float tile[32][33];
    int tx = threadIdx.x & 31, ty = threadIdx.x >> 5;
    int bx = blockIdx.x * 32, by = blockIdx.y * 32;
    for (int i = 0; i < 32; i += 8) {
        int r = by + ty + i, c = bx + tx;
        if (r < R && c < C) tile[ty + i][tx] = src[r*C + c];
    }
    __syncthreads();
    for (int i = 0; i < 32; i += 8) {
        int r = by + tx, c = bx + ty + i;
        if (r < R && c < C) dst[c*R + r] = tile[tx][ty + i];
    }
}

__global__ void gates_reorder(const float* __restrict__ Wih, const float* __restrict__ Whh) {
    int id = blockIdx.x * 256 + threadIdx.x;
    int c = id & 2047;
    int k = (id >> 11) & 1023;
    int l = id >> 21;
    int gi = c >> 2, g = c & 3;
    int row = l*G4 + g*512 + gi;
    float v = (k < 512) ? Wih[row*512 + k] : Whh[row*512 + (k - 512)];
    g_Wg[id] = v;
}

// merged t0 (40 blocks) || kv (3136 blocks) || init (64 blocks)  => grid 3240
__global__ void prep_misc(const float* __restrict__ pooled, const float* __restrict__ embed,
                          const int* __restrict__ sos,  const float* __restrict__ chan,
                          const float* __restrict__ Wk, const float* __restrict__ bk,
                          const float* __restrict__ Wv, const float* __restrict__ bv,
                          const float* __restrict__ projb, float* __restrict__ res) {
    int blk = blockIdx.x, tid = threadIdx.x;
    if (blk < 40) {
        int v = blk*256 + tid;
        if (v < Vv) {
            int sv = sos[0];
            float acc = projb[v];
            for (int d = 0; d < Hh; d++) acc += embed[sv*Hh + d] * g_projWT[d*Vv + v];
            for (int b = 0; b < Bz; b++) res[b*(Vv*Tt) + v*Tt] = acc;
        }
    } else if (blk < 40 + 3136) {
        int id = (blk - 40)*256 + tid;
        int d = id & 511;
        int r = id >> 9;
        int s = r % Ss;
        int b = r / Ss;
        const float* cp  = &chan[(b*Hh + d)*Ss];
        const float* wkp = &Wk[s*Ss];
        const float* wvp = &Wv[s*Ss];
        float aK = bk[s], aV = bv[s];
#pragma unroll
        for (int k = 0; k < Ss; k++) { float c = cp[k]; aK += c*wkp[k]; aV += c*wvp[k]; }
        g_keysT[(b*Ss + s)*Hh + d]  = tanhf(aK);
        g_valsSD[(b*Ss + s)*Hh + d] = tanhf(aV);
    } else {
        // init: 64 blocks x 256 threads = 16384 = Bz*Hh  (R6/R7 bug: only 4 blocks)
        int i = (blk - (40 + 3136))*256 + tid;
        if (i < Bz*Hh) {
            int d = i & (Hh - 1);
            g_emb[i] = embed[sos[0]*Hh + d];
            float p = pooled[i];
            g_hF[i] = p; g_hF[Bz*Hh + i] = p;
            g_c[i]  = p; g_c[Bz*Hh + i]  = p;
        }
    }
}

// ---------------- host launcher ----------------
extern "C" void kernel_launch(void* const* d_in, const int* in_sizes, int n_in,
                              void* d_out, int out_size) {
    const float* img    = (const float*)d_in[0];
    const float* pooled = (const float*)d_in[1];
    const float* embed  = (const float*)d_in[2];
    const float* Wq     = (const float*)d_in[3];
    const float* bq     = (const float*)d_in[4];
    const float* Wk     = (const float*)d_in[5];
    const float* bk     = (const float*)d_in[6];
    const float* Wv     = (const float*)d_in[7];
    const float* bv     = (const float*)d_in[8];
    const float* Wih    = (const float*)d_in[9];
    const float* Whh    = (const float*)d_in[10];
    const float* bih    = (const float*)d_in[11];
    const float* bhh    = (const float*)d_in[12];
    const float* projW  = (const float*)d_in[13];
    const float* projb  = (const float*)d_in[14];
    const float* hattW  = (const float*)d_in[15];
    const float* hattb  = (const float*)d_in[16];
    const int*   sos    = (const int*)d_in[17];
    float* res = (float*)d_out;

    void *pProjWT, *pWqT, *pHattWT;
    cudaGetSymbolAddress(&pProjWT, g_projWT);
    cudaGetSymbolAddress(&pWqT,    g_WqT);
    cudaGetSymbolAddress(&pHattWT, g_hattWT);

    cudaFuncSetAttribute(loop_kernel, cudaFuncAttributeMaxDynamicSharedMemorySize, SMEM_BYTES);

    // launches 1-5 (prep), launch 6 = loop_kernel (ncu -s 5 -c 1 captures it)
    transpose_tiled<<<dim3(16, 313), 256>>>(projW, (float*)pProjWT, Vv, Hh);
    transpose_tiled<<<dim3(16, 16),  256>>>(Wq,    (float*)pWqT,    Hh, Hh);
    transpose_tiled<<<dim3(32, 16),  256>>>(hattW, (float*)pHattWT, Hh, 2*Hh);
    gates_reorder<<<(2*1024*G4)/256, 256>>>(Wih, Whh);
    prep_misc<<<40 + 3136 + 64, 256>>>(pooled, embed, sos, img, Wk, bk, Wv, bv, projb, res);

    loop_kernel<<<NBLK, 256, SMEM_BYTES>>>(bih, bhh, projb, bq, hattb, embed, res);
}

// round 9
// speedup vs baseline: 1.2203x; 1.0251x over previous
#include <cuda_runtime.h>
#include <math.h>

#define Bz 32
#define Hh 512
#define Vv 10000
#define Tt 20
#define Ss 49
#define G4 2048
#define NBLK 148
#define NTILES 313
#define SM_FLOATS (32*1024 + 32*32 + 64)
#define SMEM_BYTES (SM_FLOATS * 4)

// ---------------- device scratch ----------------
__device__ float g_keysT[Bz*Ss*Hh];      // [b][s][d]
__device__ float g_valsSD[Bz*Ss*Hh];     // [b][s][d]
__device__ float g_h[2*Bz*Hh];           // post-cell hidden
__device__ float g_hF[2*Bz*Hh];          // post-attention hidden
__device__ float g_c[2*Bz*Hh];
__device__ float g_emb[Bz*Hh];
__device__ float g_q[2*Bz*Hh];
__device__ float g_attn[2*Bz*Hh];
__device__ float g_pmax[NTILES*Bz];
__device__ int   g_pidx[NTILES*Bz];
__device__ int   g_tok[Bz];
__device__ float g_Wg[2*1024*G4];        // [l][k(1024: ih|hh)][gi*4+gate]
__device__ float g_projWT[Hh*Vv + 64];   // [d][v] (+pad for OOB-safe prefetch)
__device__ float g_WqT[Hh*Hh];           // [k][d]
__device__ float g_hattWT[2*Hh*Hh];      // [k(1024)][d]
__device__ unsigned g_bar_count;         // zero-init
__device__ unsigned g_bar_gen;           // zero-init, monotonic across replays

__device__ __forceinline__ float sigm(float x) { return 1.0f / (1.0f + expf(-x)); }

// ---------------- grid barrier: TIGHT spin (no nanosleep — testing the
// ---------------- hypothesis that nanosleep's wakeup quantum dominated) ----------------
__device__ __forceinline__ unsigned ld_relaxed_gpu(unsigned* p) {
    unsigned v;
    asm volatile("ld.relaxed.gpu.global.u32 %0, [%1];" : "=r"(v) : "l"(p) : "memory");
    return v;
}
__device__ __forceinline__ void gsync(unsigned &mygen) {
    __syncthreads();
    mygen++;
    if (threadIdx.x == 0) {
        unsigned old;
        asm volatile("atom.release.gpu.global.add.u32 %0, [%1], %2;"
                     : "=r"(old) : "l"(&g_bar_count), "r"(1u) : "memory");
        if (old == NBLK - 1) {
            asm volatile("st.relaxed.gpu.global.u32 [%0], %1;"
                         :: "l"(&g_bar_count), "r"(0u) : "memory");
            asm volatile("st.release.gpu.global.u32 [%0], %1;"
                         :: "l"(&g_bar_gen), "r"(mygen) : "memory");
        } else {
            while (ld_relaxed_gpu(&g_bar_gen) < mygen) { }
        }
        __threadfence();   // CCTL.IVALL: L1 invalidate + ordering after relaxed spin
    }
    __syncthreads();
}

// ---------------- gates + cell, one layer (relative blocks 0..63) ----------------
__device__ void phase_gates(int l, float* S, const float* __restrict__ bih,
                            const float* __restrict__ bhh) {
    int tid = threadIdx.x, blk = blockIdx.x;
    float* sX = S;                  // [32][1024]  (x | h_rec)
    float* sg = S + 32*1024;        // [32 cols][32 b]
    const float4* x4 = (const float4*)((l == 0) ? g_emb : g_h);
    const float4* h4 = (const float4*)(g_hF + l*Bz*Hh);
    float4* d4 = (float4*)sX;
    for (int i = tid; i < 32*128; i += 256) {
        int b = i >> 7, kq = i & 127;
        d4[b*256 + kq]       = x4[i];
        d4[b*256 + 128 + kq] = h4[i];
    }
    __syncthreads();

    int lane = tid & 31, bg = tid >> 5;
    const float* W = g_Wg + l*(1024*G4) + blk*32 + lane;
    const float* a0 = &sX[(bg*4 + 0)*1024];
    const float* a1 = &sX[(bg*4 + 1)*1024];
    const float* a2 = &sX[(bg*4 + 2)*1024];
    const float* a3 = &sX[(bg*4 + 3)*1024];
    float acc0 = 0.f, acc1 = 0.f, acc2 = 0.f, acc3 = 0.f;
#pragma unroll 4
    for (int k = 0; k < 1024; k += 4) {
        const float* wp = W + k*G4;
        float w0 = wp[0], w1 = wp[G4], w2 = wp[2*G4], w3 = wp[3*G4];
        float4 v0 = *(const float4*)&a0[k];
        float4 v1 = *(const float4*)&a1[k];
        float4 v2 = *(const float4*)&a2[k];
        float4 v3 = *(const float4*)&a3[k];
        acc0 += v0.x*w0 + v0.y*w1 + v0.z*w2 + v0.w*w3;
        acc1 += v1.x*w0 + v1.y*w1 + v1.z*w2 + v1.w*w3;
        acc2 += v2.x*w0 + v2.y*w1 + v2.z*w2 + v2.w*w3;
        acc3 += v3.x*w0 + v3.y*w1 + v3.z*w2 + v3.w*w3;
    }
    sg[lane*32 + bg*4 + 0] = acc0;
    sg[lane*32 + bg*4 + 1] = acc1;
    sg[lane*32 + bg*4 + 2] = acc2;
    sg[lane*32 + bg*4 + 3] = acc3;
    __syncthreads();

    int gi_l = tid >> 5, b = tid & 31;
    int gi = blk*8 + gi_l;
    const float* bi = bih + l*G4; const float* bh = bhh + l*G4;
    float vi = sg[(gi_l*4 + 0)*32 + b] + bi[gi]        + bh[gi];
    float vf = sg[(gi_l*4 + 1)*32 + b] + bi[512 + gi]  + bh[512 + gi];
    float vg = sg[(gi_l*4 + 2)*32 + b] + bi[1024 + gi] + bh[1024 + gi];
    float vo = sg[(gi_l*4 + 3)*32 + b] + bi[1536 + gi] + bh[1536 + gi];
    int idx = (l*Bz + b)*Hh + gi;
    float c  = g_c[idx];
    float cn = sigm(vf)*c + sigm(vi)*tanhf(vg);
    g_c[idx] = cn;
    g_h[idx] = sigm(vo)*tanhf(cn);
}

// ---------------- batched q-GEMM: 16 blocks x 32 d-cols ----------------
__device__ void phase_q(int l, int qb, float* S, const float* __restrict__ bq) {
    int tid = threadIdx.x;
    float* sH = S;
    const float4* h4 = (const float4*)(g_h + l*Bz*Hh);
    float4* s4 = (float4*)sH;
    for (int i = tid; i < Bz*Hh/4; i += 256) s4[i] = h4[i];
    __syncthreads();

    int lane = tid & 31, bg = tid >> 5;
    int d = qb*32 + lane;
    float acc0 = 0.f, acc1 = 0.f, acc2 = 0.f, acc3 = 0.f;
    const float* a0 = &sH[(bg*4 + 0)*Hh];
    const float* a1 = &sH[(bg*4 + 1)*Hh];
    const float* a2 = &sH[(bg*4 + 2)*Hh];
    const float* a3 = &sH[(bg*4 + 3)*Hh];
#pragma unroll 4
    for (int k = 0; k < Hh; k += 4) {
        const float* wp = &g_WqT[k*Hh + d];
        float w0 = wp[0], w1 = wp[Hh], w2 = wp[2*Hh], w3 = wp[3*Hh];
        float4 v0 = *(const float4*)&a0[k];
        float4 v1 = *(const float4*)&a1[k];
        float4 v2 = *(const float4*)&a2[k];
        float4 v3 = *(const float4*)&a3[k];
        acc0 += v0.x*w0 + v0.y*w1 + v0.z*w2 + v0.w*w3;
        acc1 += v1.x*w0 + v1.y*w1 + v1.z*w2 + v1.w*w3;
        acc2 += v2.x*w0 + v2.y*w1 + v2.z*w2 + v2.w*w3;
        acc3 += v3.x*w0 + v3.y*w1 + v3.z*w2 + v3.w*w3;
    }
    float bv = bq[d];
    g_q[(l*Bz + bg*4 + 0)*Hh + d] = tanhf(acc0 + bv);
    g_q[(l*Bz + bg*4 + 1)*Hh + d] = tanhf(acc1 + bv);
    g_q[(l*Bz + bg*4 + 2)*Hh + d] = tanhf(acc2 + bv);
    g_q[(l*Bz + bg*4 + 3)*Hh + d] = tanhf(acc3 + bv);
}

// ---------------- scores + softmax + attn vector for 2 batches ----------------
__device__ void phase_att(int l, int b0, float* S) {
    int tid = threadIdx.x;
    float* sq   = S;            // [2][512]
    float* ssc  = S + 1024;
    float* sw   = S + 1152;
    float* smax = S + 1280;
    float* sinv = S + 1284;
    for (int i = tid; i < 2*Hh; i += 256) {
        int bb = i >> 9;
        sq[i] = g_q[(l*Bz + b0 + bb)*Hh + (i & 511)];
    }
    __syncthreads();

    int warp = tid >> 5, lane = tid & 31;
    int half = warp >> 2, w2 = warp & 3;
    int b = b0 + half;
    for (int s = w2; s < Ss; s += 4) {
        const float* kp = &g_keysT[(b*Ss + s)*Hh];
        const float* qp = &sq[half*Hh];
        float p = 0.f;
        for (int d = lane; d < Hh; d += 32) p += qp[d]*kp[d];
#pragma unroll
        for (int o = 16; o; o >>= 1) p += __shfl_xor_sync(0xffffffffu, p, o);
        if (lane == 0) ssc[half*64 + s] = p * (1.0f/7.0f);
    }
    __syncthreads();
    if (tid < 2) {
        float mx = -INFINITY;
        for (int s = 0; s < Ss; s++) mx = fmaxf(mx, ssc[tid*64 + s]);
        smax[tid] = mx;
    }
    __syncthreads();
    if (tid < 128) {
        int bb = tid >> 6, s = tid & 63;
        if (s < Ss) sw[bb*64 + s] = expf(ssc[bb*64 + s] - smax[bb]);
    }
    __syncthreads();
    if (tid < 2) {
        float sum = 0.f;
        for (int s = 0; s < Ss; s++) sum += sw[tid*64 + s];
        sinv[tid] = 1.0f / sum;
    }
    __syncthreads();
#pragma unroll
    for (int rep = 0; rep < 4; rep++) {
        int idx = rep*256 + tid;
        int bb = idx >> 9, d = idx & 511;
        const float* wv = &sw[bb*64];
        float a = 0.f;
#pragma unroll
        for (int s = 0; s < Ss; s++)
            a += wv[s] * g_valsSD[((b0 + bb)*Ss + s)*Hh + d];
        g_attn[(l*Bz + b0 + bb)*Hh + d] = a * sinv[bb];
    }
}

// ---------------- hatt GEMM: 64 rel-blocks = 16 d-groups x 4 b-quads(8b) ----------------
__device__ void phase_hatt(int l, int rb, float* S, const float* __restrict__ hattb) {
    int tid = threadIdx.x;
    int dg = rb >> 2, bq4 = rb & 3;
    int b0 = bq4*8;
    float* sX = S;               // [8][1024]
    float* sred = S + 8*1024;    // [256][8]
    for (int i = tid; i < 8*1024; i += 256) {
        int b = i >> 10, kk = i & 1023;
        float v = (kk < 512) ? g_attn[(l*Bz + b0 + b)*Hh + kk]
                             : g_h[(l*Bz + b0 + b)*Hh + (kk - 512)];
        sX[i] = v;
    }
    __syncthreads();

    int lane = tid & 31, w = tid >> 5;
    int d = dg*32 + lane;
    float acc[8];
#pragma unroll
    for (int j = 0; j < 8; j++) acc[j] = 0.f;
    int k0 = w*128;
#pragma unroll 2
    for (int kk = k0; kk < k0 + 128; kk += 4) {
        const float* wp = &g_hattWT[kk*Hh + d];
        float w0 = wp[0], w1 = wp[Hh], w2 = wp[2*Hh], w3 = wp[3*Hh];
#pragma unroll
        for (int j = 0; j < 8; j++) {
            float4 a = *(const float4*)&sX[j*1024 + kk];
            acc[j] += a.x*w0 + a.y*w1 + a.z*w2 + a.w*w3;
        }
    }
#pragma unroll
    for (int j = 0; j < 8; j++) sred[(w*32 + lane)*8 + j] = acc[j];
    __syncthreads();

    int d_l = tid >> 3, j = tid & 7;
    float s = 0.f;
#pragma unroll
    for (int w2 = 0; w2 < 8; w2++) s += sred[(w2*32 + d_l)*8 + j];
    int dd = dg*32 + d_l;
    g_hF[(l*Bz + b0 + j)*Hh + dd] = tanhf(s + hattb[dd]);
}

// ---------------- logits tile with smem-buffered W (32 v x 32 b) ----------------
__device__ void logit_tile_smem(const float* __restrict__ sH, float* __restrict__ sW,
                                int tile, int t,
                                const float* __restrict__ projb, float* __restrict__ res) {
    int tid = threadIdx.x;
    int vl = tid & 31, bg = tid >> 5;
    int v  = tile*32 + vl;
    int v0 = tile*32;
    bool valid = (v < Vv);

    int f0 = tid, f1 = tid + 256;
    int row0 = f0 >> 3, q0 = (f0 & 7)*4;
    int row1 = f1 >> 3, q1 = (f1 & 7)*4;

    float4 r0 = *(const float4*)&g_projWT[row0*Vv + v0 + q0];
    float4 r1 = *(const float4*)&g_projWT[row1*Vv + v0 + q1];
    *(float4*)&sW[f0*4] = r0;
    *(float4*)&sW[f1*4] = r1;
    __syncthreads();

    float acc0 = 0.f, acc1 = 0.f, acc2 = 0.f, acc3 = 0.f;
    int buf = 0;
#pragma unroll
    for (int c = 0; c < 8; c++) {
        if (c < 7) {
            r0 = *(const float4*)&g_projWT[((c+1)*64 + row0)*Vv + v0 + q0];
            r1 = *(const float4*)&g_projWT[((c+1)*64 + row1)*Vv + v0 + q1];
        }
        const float* wc = sW + buf*2048;
        const float* h0 = &sH[(bg*4 + 0)*Hh + c*64];
        const float* h1 = &sH[(bg*4 + 1)*Hh + c*64];
        const float* h2 = &sH[(bg*4 + 2)*Hh + c*64];
        const float* h3 = &sH[(bg*4 + 3)*Hh + c*64];
#pragma unroll
        for (int dl = 0; dl < 64; dl += 4) {
            float w0 = wc[dl*32 + vl];
            float w1 = wc[(dl+1)*32 + vl];
            float w2 = wc[(dl+2)*32 + vl];
            float w3 = wc[(dl+3)*32 + vl];
            float4 a0 = *(const float4*)&h0[dl];
            float4 a1 = *(const float4*)&h1[dl];
            float4 a2 = *(const float4*)&h2[dl];
            float4 a3 = *(const float4*)&h3[dl];
            acc0 += a0.x*w0 + a0.y*w1 + a0.z*w2 + a0.w*w3;
            acc1 += a1.x*w0 + a1.y*w1 + a1.z*w2 + a1.w*w3;
            acc2 += a2.x*w0 + a2.y*w1 + a2.z*w2 + a2.w*w3;
            acc3 += a3.x*w0 + a3.y*w1 + a3.z*w2 + a3.w*w3;
        }
        if (c < 7) {
            int nb = buf ^ 1;
            *(float4*)&sW[nb*2048 + f0*4] = r0;
            *(float4*)&sW[nb*2048 + f1*4] = r1;
            __syncthreads();
            buf = nb;
        }
    }

    float pb = projb[valid ? v : (Vv - 1)];
    float a[4] = {acc0, acc1, acc2, acc3};
#pragma unroll
    for (int i = 0; i < 4; i++) {
        int b = bg*4 + i;
        float r = a[i] + pb;
        if (valid) res[b*(Vv*Tt) + v*Tt + t] = r;
        float mv = valid ? r : -INFINITY;
        int   mi = v;
#pragma unroll
        for (int o = 16; o; o >>= 1) {
            float ov = __shfl_xor_sync(0xffffffffu, mv, o);
            int   oi = __shfl_xor_sync(0xffffffffu, mi, o);
            if (ov > mv || (ov == mv && oi < mi)) { mv = ov; mi = oi; }
        }
        if (vl == 0) { g_pmax[tile*32 + b] = mv; g_pidx[tile*32 + b] = mi; }
    }
    __syncthreads();
}

// ---------------- phase C logits driver: blocks 0..115, 313 tiles ----------------
__device__ void phase_logitsC(float* S, const float* __restrict__ projb,
                              float* __restrict__ res, int t) {
    int tid = threadIdx.x, blk = blockIdx.x;
    const float4* H4 = (const float4*)(g_h + Bz*Hh);
    float4* S4 = (float4*)S;
    for (int i = tid; i < Bz*Hh/4; i += 256) S4[i] = H4[i];
    __syncthreads();
    float* sW = S + 16384;
    logit_tile_smem(S, sW, blk*2,     t, projb, res);
    logit_tile_smem(S, sW, blk*2 + 1, t, projb, res);
    if (blk < 81) logit_tile_smem(S, sW, 232 + blk, t, projb, res);
}

// ---------------- argmax finalize + embedding gather ----------------
__device__ void phase_argmax(float* S, const float* __restrict__ embed) {
    int tid = threadIdx.x;
    float* sv = S;
    int* si = (int*)(S + 256);
    int b = tid & 31, j = tid >> 5;
    float mv = -INFINITY; int mi = 0;
    for (int tl = j; tl < NTILES; tl += 8) {
        float v = g_pmax[tl*32 + b]; int ix = g_pidx[tl*32 + b];
        if (v > mv || (v == mv && ix < mi)) { mv = v; mi = ix; }
    }
    sv[j*32 + b] = mv; si[j*32 + b] = mi;
    __syncthreads();
    if (tid < 32) {
        float bv = sv[b]; int bi = si[b];
        for (int j2 = 1; j2 < 8; j2++) {
            float v = sv[j2*32 + b]; int ix = si[j2*32 + b];
            if (v > bv || (v == bv && ix < bi)) { bv = v; bi = ix; }
        }
        g_tok[b] = bi;
    }
    __syncthreads();
    for (int i = tid; i < Bz*Hh; i += 256) {
        int bb = i >> 9, d = i & 511;
        g_emb[i] = embed[g_tok[bb]*Hh + d];
    }
}

// ---------------- t0: res[:, :, 0] (blocks 128..147, t==0 only) ----------------
__device__ void phase_t0(const float* __restrict__ projb, float* __restrict__ res) {
    int rb = blockIdx.x - 128, tid = threadIdx.x;
#pragma unroll
    for (int rep = 0; rep < 2; rep++) {
        int v = rb*512 + rep*256 + tid;
        if (v < Vv) {
            float acc = projb[v];
            for (int d = 0; d < Hh; d++) acc += g_emb[d] * g_projWT[d*Vv + v];
            for (int b = 0; b < Bz; b++) res[b*(Vv*Tt) + v*Tt] = acc;
        }
    }
}

// ---------------- prep: transposes + reorder + kv + init (all blocks) ----------------
__device__ void prep_transpose_tile(const float* __restrict__ src, float* __restrict__ dst,
                                    int R, int C, int bx, int by, float* S) {
    float (*tile)[33] = (float(*)[33])S;
    int tx = threadIdx.x & 31, ty = threadIdx.x >> 5;
#pragma unroll
    for (int i = 0; i < 32; i += 8) {
        int r = by*32 + ty + i, c = bx*32 + tx;
        if (r < R && c < C) tile[ty + i][tx] = src[r*C + c];
    }
    __syncthreads();
#pragma unroll
    for (int i = 0; i < 32; i += 8) {
        int r = by*32 + tx, c = bx*32 + ty + i;
        if (r < R && c < C) dst[c*R + r] = tile[tx][ty + i];
    }
    __syncthreads();
}

__device__ void phase_prep(const float* __restrict__ projW, const float* __restrict__ Wq,
                           const float* __restrict__ hattW, const float* __restrict__ Wih,
                           const float* __restrict__ Whh,  const float* __restrict__ pooled,
                           const float* __restrict__ embed, const int* __restrict__ sos,
                           const float* __restrict__ chan, const float* __restrict__ Wk,
                           const float* __restrict__ bk,   const float* __restrict__ Wv,
                           const float* __restrict__ bv,   float* S) {
    int blk = blockIdx.x, tid = threadIdx.x;
    // 5008 projW tiles + 256 Wq tiles + 512 hattW tiles = 5776
    for (int task = blk; task < 5776; task += NBLK) {
        if (task < 5008)      prep_transpose_tile(projW, g_projWT, Vv, Hh, task % 16, task / 16, S);
        else if (task < 5264) { int t2 = task - 5008; prep_transpose_tile(Wq, g_WqT, Hh, Hh, t2 % 16, t2 / 16, S); }
        else                  { int t3 = task - 5264; prep_transpose_tile(hattW, g_hattWT, Hh, 2*Hh, t3 % 32, t3 / 32, S); }
    }
    // gate-weight reorder
    for (int id = blk*256 + tid; id < 2*1024*G4; id += NBLK*256) {
        int c = id & 2047;
        int k = (id >> 11) & 1023;
        int l = id >> 21;
        int gi = c >> 2, g = c & 3;
        int row = l*G4 + g*512 + gi;
        g_Wg[id] = (k < 512) ? Wih[row*512 + k] : Whh[row*512 + (k - 512)];
    }
    // keys / values
    for (int id = blk*256 + tid; id < Bz*Ss*Hh; id += NBLK*256) {
        int d = id & 511;
        int r = id >> 9;
        int s = r % Ss;
        int b = r / Ss;
        const float* cp  = &chan[(b*Hh + d)*Ss];
        const float* wkp = &Wk[s*Ss];
        const float* wvp = &Wv[s*Ss];
        float aK = bk[s], aV = bv[s];
#pragma unroll
        for (int k = 0; k < Ss; k++) { float c = cp[k]; aK += c*wkp[k]; aV += c*wvp[k]; }
        g_keysT[(b*Ss + s)*Hh + d]  = tanhf(aK);
        g_valsSD[(b*Ss + s)*Hh + d] = tanhf(aV);
    }
    // state init
    for (int i = blk*256 + tid; i < Bz*Hh; i += NBLK*256) {
        int d = i & (Hh - 1);
        g_emb[i] = embed[sos[0]*Hh + d];
        float p = pooled[i];
        g_hF[i] = p; g_hF[Bz*Hh + i] = p;
        g_c[i]  = p; g_c[Bz*Hh + i]  = p;
    }
}

// ---------------- THE single persistent kernel ----------------
__global__ __launch_bounds__(256, 1)
void loop_kernel(const float* __restrict__ projW, const float* __restrict__ Wq,
                 const float* __restrict__ hattW, const float* __restrict__ Wih,
                 const float* __restrict__ Whh,  const float* __restrict__ pooled,
                 const float* __restrict__ embed, const int* __restrict__ sos,
                 const float* __restrict__ chan, const float* __restrict__ Wk,
                 const float* __restrict__ bk,   const float* __restrict__ Wv,
                 const float* __restrict__ bv,
                 const float* __restrict__ bih,  const float* __restrict__ bhh,
                 const float* __restrict__ projb, const float* __restrict__ bq,
                 const float* __restrict__ hattb, float* __restrict__ res) {
    extern __shared__ float S[];
    int blk = blockIdx.x;
    unsigned mygen = 0;
    if (threadIdx.x == 0) mygen = ld_relaxed_gpu(&g_bar_gen);

    phase_prep(projW, Wq, hattW, Wih, Whh, pooled, embed, sos, chan, Wk, bk, Wv, bv, S);
    gsync(mygen);

    for (int t = 0; t < Tt - 1; t++) {
        // A: gates0 || hatt1(t-1) || t0(t==0)
        if (blk < 64) phase_gates(0, S, bih, bhh);
        else if (blk < 128) { if (t > 0) phase_hatt(1, blk - 64, S, hattb); }
        else { if (t == 0) phase_t0(projb, res); }
        gsync(mygen);
        // B: gates1 || q0
        if (blk < 64) phase_gates(1, S, bih, bhh);
        else if (blk < 80) phase_q(0, blk - 64, S, bq);
        gsync(mygen);
        // C: logits || q1 || att0
        if (blk < 116) phase_logitsC(S, projb, res, t + 1);
        else if (blk < 132) phase_q(1, blk - 116, S, bq);
        else phase_att(0, (blk - 132)*2, S);
        gsync(mygen);
        // D: hatt0 || att1 || argmax  (skipped on final step — nothing consumes it)
        if (t < Tt - 2) {
            if (blk < 64) phase_hatt(0, blk, S, hattb);
            else if (blk < 80) phase_att(1, (blk - 64)*2, S);
            else if (blk == 80) phase_argmax(S, embed);
            gsync(mygen);
        }
    }
}

// ---------------- host launcher: ONE kernel ----------------
extern "C" void kernel_launch(void* const* d_in, const int* in_sizes, int n_in,
                              void* d_out, int out_size) {
    const float* img    = (const float*)d_in[0];
    const float* pooled = (const float*)d_in[1];
    const float* embed  = (const float*)d_in[2];
    const float* Wq     = (const float*)d_in[3];
    const float* bq     = (const float*)d_in[4];
    const float* Wk     = (const float*)d_in[5];
    const float* bk     = (const float*)d_in[6];
    const float* Wv     = (const float*)d_in[7];
    const float* bv     = (const float*)d_in[8];
    const float* Wih    = (const float*)d_in[9];
    const float* Whh    = (const float*)d_in[10];
    const float* bih    = (const float*)d_in[11];
    const float* bhh    = (const float*)d_in[12];
    const float* projW  = (const float*)d_in[13];
    const float* projb  = (const float*)d_in[14];
    const float* hattW  = (const float*)d_in[15];
    const float* hattb  = (const float*)d_in[16];
    const int*   sos    = (const int*)d_in[17];
    float* res = (float*)d_out;

    cudaFuncSetAttribute(loop_kernel, cudaFuncAttributeMaxDynamicSharedMemorySize, SMEM_BYTES);

    loop_kernel<<<NBLK, 256, SMEM_BYTES>>>(projW, Wq, hattW, Wih, Whh, pooled, embed, sos,
                                           img, Wk, bk, Wv, bv,
                                           bih, bhh, projb, bq, hattb, res);
}

// round 11
// speedup vs baseline: 1.2430x; 1.0186x over previous
#include <cuda_runtime.h>
#include <math.h>

#define Bz 32
#define Hh 512
#define Vv 10000
#define Tt 20
#define Ss 49
#define G4 2048

// ---------------- device scratch ----------------
__device__ float g_keysT[Bz*Ss*Hh];      // [b][s][d]
__device__ float g_valsSD[Bz*Ss*Hh];     // [b][s][d]
__device__ float g_h[2*Bz*Hh];           // post-cell hidden
__device__ float g_hF[2*Bz*Hh];          // post-attention hidden (recurrent input)
__device__ float g_c[2*Bz*Hh];
__device__ float g_emb[Bz*Hh];
__device__ float g_q[2*Bz*Hh];
__device__ float g_attn[2*Bz*Hh];
__device__ float g_logits[Bz*Vv];
__device__ float g_gpart[4*Bz*G4];
__device__ float g_WihT[2*Hh*G4];        // [l][k][j]
__device__ float g_WhhT[2*Hh*G4];
__device__ float g_projWT[Hh*Vv];        // [d][v]
__device__ float g_WqT[Hh*Hh];           // [k][d]
__device__ float g_hattWT[2*Hh*Hh];      // [k][d]

__device__ __forceinline__ float sigm(float x) { return 1.0f / (1.0f + expf(-x)); }

// ================= PREP =================

// all weight transposes in one grid-stride kernel (9872 32x32 tile tasks)
__global__ void prep_transposes(const float* __restrict__ projW, const float* __restrict__ Wih,
                                const float* __restrict__ Whh,  const float* __restrict__ Wq,
                                const float* __restrict__ hattW) {
    __shared__ float tile[32][33];
    int tx = threadIdx.x & 31, ty = threadIdx.x >> 5;
    for (int task = blockIdx.x; task < 9872; task += gridDim.x) {
        const float* src; float* dst; int R, C, bx, by;
        if (task < 5008)      { src = projW;            dst = g_projWT;           R = Vv; C = Hh;  bx = task % 16;          by = task / 16; }
        else if (task < 6032) { int u = task - 5008;    src = Wih;                dst = g_WihT;             R = G4; C = Hh;  bx = u % 16; by = u / 16; }
        else if (task < 7056) { int u = task - 6032;    src = Wih + G4*Hh;        dst = g_WihT + Hh*G4;     R = G4; C = Hh;  bx = u % 16; by = u / 16; }
        else if (task < 8080) { int u = task - 7056;    src = Whh;                dst = g_WhhT;             R = G4; C = Hh;  bx = u % 16; by = u / 16; }
        else if (task < 9104) { int u = task - 8080;    src = Whh + G4*Hh;        dst = g_WhhT + Hh*G4;     R = G4; C = Hh;  bx = u % 16; by = u / 16; }
        else if (task < 9360) { int u = task - 9104;    src = Wq;                 dst = g_WqT;              R = Hh; C = Hh;  bx = u % 16; by = u / 16; }
        else                  { int u = task - 9360;    src = hattW;              dst = g_hattWT;           R = Hh; C = 2*Hh; bx = u % 32; by = u / 32; }
        for (int i = 0; i < 32; i += 8) {
            int r = by*32 + ty + i, c = bx*32 + tx;
            if (r < R && c < C) tile[ty + i][tx] = src[r*C + c];
        }
        __syncthreads();
        for (int i = 0; i < 32; i += 8) {
            int r = by*32 + tx, c = bx*32 + ty + i;
            if (r < R && c < C) dst[c*R + r] = tile[tx][ty + i];
        }
        __syncthreads();
    }
}

// keys/values in [b][s][d] layout
__global__ void prep_kv(const float* __restrict__ chan,
                        const float* __restrict__ Wk, const float* __restrict__ bk,
                        const float* __restrict__ Wv, const float* __restrict__ bv) {
    int id = blockIdx.x * 256 + threadIdx.x;   // < 802816
    int d = id & 511;
    int r = id >> 9;
    int s = r % Ss;
    int b = r / Ss;
    const float* cp  = &chan[(b*Hh + d)*Ss];
    const float* wkp = &Wk[s*Ss];
    const float* wvp = &Wv[s*Ss];
    float aK = bk[s], aV = bv[s];
#pragma unroll
    for (int k = 0; k < Ss; k++) { float c = cp[k]; aK += c*wkp[k]; aV += c*wvp[k]; }
    g_keysT[(b*Ss + s)*Hh + d]  = tanhf(aK);
    g_valsSD[(b*Ss + s)*Hh + d] = tanhf(aV);
}

// t0 column (blocks 0..39) + state init (blocks 40..103)
__global__ void prep_init_t0(const float* __restrict__ pooled, const float* __restrict__ embed,
                             const int* __restrict__ sos, const float* __restrict__ projb,
                             float* __restrict__ res) {
    int blk = blockIdx.x, tid = threadIdx.x;
    if (blk < 40) {
        int v = blk*256 + tid;
        if (v < Vv) {
            int sv = sos[0];
            float acc = projb[v];
            for (int d = 0; d < Hh; d++) acc += embed[sv*Hh + d] * g_projWT[d*Vv + v];
            for (int b = 0; b < Bz; b++) res[b*(Vv*Tt) + v*Tt] = acc;
        }
    } else {
        int i = (blk - 40)*256 + tid;   // 64 blocks -> 16384 = Bz*Hh
        int d = i & (Hh - 1);
        g_emb[i] = embed[sos[0]*Hh + d];
        float p = pooled[i];
        g_hF[i] = p; g_hF[Bz*Hh + i] = p;
        g_c[i]  = p; g_c[Bz*Hh + i]  = p;
    }
}

// ================= STEP KERNELS (gates/cell/logits = R1 bodies) =================

// grid (32, 4): x = 64-wide j chunk, y = 256-wide reduction slice (y<2: x-part, else h-part)
__global__ __launch_bounds__(256) void gates_kernel(int l) {
    __shared__ float sh[32 * 256];
    int tid = threadIdx.x;
    int y = blockIdx.y;
    const float* src = (y < 2) ? ((l == 0) ? g_emb : g_h) : (g_hF + l * Bz * Hh);
    int off = (y & 1) * 256;
    for (int b = 0; b < 32; b++)
        sh[b * 256 + tid] = src[b * Hh + off + tid];
    __syncthreads();

    const float* WT = ((y < 2) ? g_WihT : g_WhhT) + l * Hh * G4;
    int kbase = (y & 1) * 256;
    int jl = tid & 63, bg = tid >> 6;
    int j = blockIdx.x * 64 + jl;

    float acc0=0,acc1=0,acc2=0,acc3=0,acc4=0,acc5=0,acc6=0,acc7=0;
    const float* shb = &sh[bg * 8 * 256];
#pragma unroll 4
    for (int mi = 0; mi < 256; mi += 4) {
        const float* wp = &WT[(kbase + mi) * G4 + j];
        float w0 = wp[0], w1 = wp[G4], w2 = wp[2*G4], w3 = wp[3*G4];
        float4 v0 = *(const float4*)&shb[0*256 + mi];
        float4 v1 = *(const float4*)&shb[1*256 + mi];
        float4 v2 = *(const float4*)&shb[2*256 + mi];
        float4 v3 = *(const float4*)&shb[3*256 + mi];
        float4 v4 = *(const float4*)&shb[4*256 + mi];
        float4 v5 = *(const float4*)&shb[5*256 + mi];
        float4 v6 = *(const float4*)&shb[6*256 + mi];
        float4 v7 = *(const float4*)&shb[7*256 + mi];
        acc0 += v0.x*w0 + v0.y*w1 + v0.z*w2 + v0.w*w3;
        acc1 += v1.x*w0 + v1.y*w1 + v1.z*w2 + v1.w*w3;
        acc2 += v2.x*w0 + v2.y*w1 + v2.z*w2 + v2.w*w3;
        acc3 += v3.x*w0 + v3.y*w1 + v3.z*w2 + v3.w*w3;
        acc4 += v4.x*w0 + v4.y*w1 + v4.z*w2 + v4.w*w3;
        acc5 += v5.x*w0 + v5.y*w1 + v5.z*w2 + v5.w*w3;
        acc6 += v6.x*w0 + v6.y*w1 + v6.z*w2 + v6.w*w3;
        acc7 += v7.x*w0 + v7.y*w1 + v7.z*w2 + v7.w*w3;
    }
    int bb = bg * 8;
    g_gpart[(y*32 + bb+0)*G4 + j] = acc0;
    g_gpart[(y*32 + bb+1)*G4 + j] = acc1;
    g_gpart[(y*32 + bb+2)*G4 + j] = acc2;
    g_gpart[(y*32 + bb+3)*G4 + j] = acc3;
    g_gpart[(y*32 + bb+4)*G4 + j] = acc4;
    g_gpart[(y*32 + bb+5)*G4 + j] = acc5;
    g_gpart[(y*32 + bb+6)*G4 + j] = acc6;
    g_gpart[(y*32 + bb+7)*G4 + j] = acc7;
}

__global__ void cell_kernel(int l, const float* __restrict__ bih,
                            const float* __restrict__ bhh) {
    int b = blockIdx.x, j = threadIdx.x;
    const float* bi = &bih[l * G4];
    const float* bh = &bhh[l * G4];
    float gi = bi[j]        + bh[j];
    float gf = bi[512 + j]  + bh[512 + j];
    float gg = bi[1024 + j] + bh[1024 + j];
    float go = bi[1536 + j] + bh[1536 + j];
#pragma unroll
    for (int ks = 0; ks < 4; ks++) {
        const float* gp = &g_gpart[(ks * 32 + b) * G4];
        gi += gp[j]; gf += gp[512 + j]; gg += gp[1024 + j]; go += gp[1536 + j];
    }
    int idx = (l * Bz + b) * Hh + j;
    float c  = g_c[idx];
    float cn = sigm(gf) * c + sigm(gi) * tanhf(gg);
    g_c[idx] = cn;
    g_h[idx] = sigm(go) * tanhf(cn);
}

__global__ __launch_bounds__(256) void logits_kernel(const float* __restrict__ projb,
                                                     float* __restrict__ res, int t) {
    extern __shared__ float shl[];  // [32][512]
    int tid = threadIdx.x;
    const float* H1 = &g_h[Bz * Hh];
    for (int f = tid; f < Bz * Hh; f += 256) shl[f] = H1[f];
    __syncthreads();

    int vl = tid & 63, bg = tid >> 6;
    int v = blockIdx.x * 64 + vl;
    if (v >= Vv) return;

    float acc0=0,acc1=0,acc2=0,acc3=0,acc4=0,acc5=0,acc6=0,acc7=0;
    const float* shb = &shl[bg * 8 * Hh];
#pragma unroll 4
    for (int d = 0; d < Hh; d += 4) {
        const float* wp = &g_projWT[d * Vv + v];
        float w0 = wp[0], w1 = wp[Vv], w2 = wp[2*Vv], w3 = wp[3*Vv];
        float4 v0 = *(const float4*)&shb[0*Hh + d];
        float4 v1 = *(const float4*)&shb[1*Hh + d];
        float4 v2 = *(const float4*)&shb[2*Hh + d];
        float4 v3 = *(const float4*)&shb[3*Hh + d];
        float4 v4 = *(const float4*)&shb[4*Hh + d];
        float4 v5 = *(const float4*)&shb[5*Hh + d];
        float4 v6 = *(const float4*)&shb[6*Hh + d];
        float4 v7 = *(const float4*)&shb[7*Hh + d];
        acc0 += v0.x*w0 + v0.y*w1 + v0.z*w2 + v0.w*w3;
        acc1 += v1.x*w0 + v1.y*w1 + v1.z*w2 + v1.w*w3;
        acc2 += v2.x*w0 + v2.y*w1 + v2.z*w2 + v2.w*w3;
        acc3 += v3.x*w0 + v3.y*w1 + v3.z*w2 + v3.w*w3;
        acc4 += v4.x*w0 + v4.y*w1 + v4.z*w2 + v4.w*w3;
        acc5 += v5.x*w0 + v5.y*w1 + v5.z*w2 + v5.w*w3;
        acc6 += v6.x*w0 + v6.y*w1 + v6.z*w2 + v6.w*w3;
        acc7 += v7.x*w0 + v7.y*w1 + v7.z*w2 + v7.w*w3;
    }
    float pb = projb[v];
    float a[8] = {acc0,acc1,acc2,acc3,acc4,acc5,acc6,acc7};
#pragma unroll
    for (int i = 0; i < 8; i++) {
        int b = bg * 8 + i;
        float r = a[i] + pb;
        g_logits[b * Vv + v] = r;
        res[b * (Vv * Tt) + v * Tt + t] = r;
    }
}

// ================= decomposed attention (weight-efficient) =================

// grid 32: l = blk>>4, 32 d-cols per block; weights streamed once per block
__global__ __launch_bounds__(256) void q_kernel(const float* __restrict__ bq) {
    extern __shared__ float sH[];
    int tid = threadIdx.x, blk = blockIdx.x;
    int l = blk >> 4, qb = blk & 15;
    const float4* h4 = (const float4*)(g_h + l*Bz*Hh);
    float4* s4 = (float4*)sH;
    for (int i = tid; i < Bz*Hh/4; i += 256) s4[i] = h4[i];
    __syncthreads();

    int lane = tid & 31, bg = tid >> 5;
    int d = qb*32 + lane;
    float acc0 = 0.f, acc1 = 0.f, acc2 = 0.f, acc3 = 0.f;
    const float* a0 = &sH[(bg*4 + 0)*Hh];
    const float* a1 = &sH[(bg*4 + 1)*Hh];
    const float* a2 = &sH[(bg*4 + 2)*Hh];
    const float* a3 = &sH[(bg*4 + 3)*Hh];
#pragma unroll 4
    for (int k = 0; k < Hh; k += 4) {
        const float* wp = &g_WqT[k*Hh + d];
        float w0 = wp[0], w1 = wp[Hh], w2 = wp[2*Hh], w3 = wp[3*Hh];
        float4 v0 = *(const float4*)&a0[k];
        float4 v1 = *(const float4*)&a1[k];
        float4 v2 = *(const float4*)&a2[k];
        float4 v3 = *(const float4*)&a3[k];
        acc0 += v0.x*w0 + v0.y*w1 + v0.z*w2 + v0.w*w3;
        acc1 += v1.x*w0 + v1.y*w1 + v1.z*w2 + v1.w*w3;
        acc2 += v2.x*w0 + v2.y*w1 + v2.z*w2 + v2.w*w3;
        acc3 += v3.x*w0 + v3.y*w1 + v3.z*w2 + v3.w*w3;
    }
    float bv = bq[d];
    g_q[(l*Bz + bg*4 + 0)*Hh + d] = tanhf(acc0 + bv);
    g_q[(l*Bz + bg*4 + 1)*Hh + d] = tanhf(acc1 + bv);
    g_q[(l*Bz + bg*4 + 2)*Hh + d] = tanhf(acc2 + bv);
    g_q[(l*Bz + bg*4 + 3)*Hh + d] = tanhf(acc3 + bv);
}

// grid 64: blocks 0..31 = scores+softmax+attn for 2 batches; 32..63 = argmax (b = blk-32)
__global__ __launch_bounds__(256) void att_argmax_kernel(const float* __restrict__ embed) {
    __shared__ float sq[1024];
    __shared__ float ssc[128], sw[128], smax[2], sinv[2];
    __shared__ float sv[256];
    __shared__ int   si[256];
    int tid = threadIdx.x, blk = blockIdx.x;

    if (blk < 32) {
        int l = blk >> 4, b0 = (blk & 15) * 2;
        for (int i = tid; i < 2*Hh; i += 256) {
            int bb = i >> 9;
            sq[i] = g_q[(l*Bz + b0 + bb)*Hh + (i & 511)];
        }
        __syncthreads();

        int warp = tid >> 5, lane = tid & 31;
        int half = warp >> 2, w2 = warp & 3;
        int b = b0 + half;
        for (int s = w2; s < Ss; s += 4) {
            const float* kp = &g_keysT[(b*Ss + s)*Hh];
            const float* qp = &sq[half*Hh];
            float p = 0.f;
            for (int d = lane; d < Hh; d += 32) p += qp[d]*kp[d];
#pragma unroll
            for (int o = 16; o; o >>= 1) p += __shfl_xor_sync(0xffffffffu, p, o);
            if (lane == 0) ssc[half*64 + s] = p * (1.0f/7.0f);
        }
        __syncthreads();
        if (tid < 2) {
            float mx = -INFINITY;
            for (int s = 0; s < Ss; s++) mx = fmaxf(mx, ssc[tid*64 + s]);
            smax[tid] = mx;
        }
        __syncthreads();
        if (tid < 128) {
            int bb = tid >> 6, s = tid & 63;
            if (s < Ss) sw[bb*64 + s] = expf(ssc[bb*64 + s] - smax[bb]);
        }
        __syncthreads();
        if (tid < 2) {
            float sum = 0.f;
            for (int s = 0; s < Ss; s++) sum += sw[tid*64 + s];
            sinv[tid] = 1.0f / sum;
        }
        __syncthreads();
#pragma unroll
        for (int rep = 0; rep < 4; rep++) {
            int idx = rep*256 + tid;
            int bb = idx >> 9, d = idx & 511;
            const float* wv = &sw[bb*64];
            float a = 0.f;
#pragma unroll
            for (int s = 0; s < Ss; s++)
                a += wv[s] * g_valsSD[((b0 + bb)*Ss + s)*Hh + d];
            g_attn[(l*Bz + b0 + bb)*Hh + d] = a * sinv[bb];
        }
    } else {
        int b = blk - 32;
        float best = -INFINITY; int bi = 0;
        for (int v = tid; v < Vv; v += 256) {
            float x = g_logits[b * Vv + v];
            if (x > best) { best = x; bi = v; }
        }
        sv[tid] = best; si[tid] = bi;
        __syncthreads();
        for (int s = 128; s > 0; s >>= 1) {
            if (tid < s) {
                float ov = sv[tid + s]; int oi = si[tid + s];
                if (ov > sv[tid] || (ov == sv[tid] && oi < si[tid])) { sv[tid] = ov; si[tid] = oi; }
            }
            __syncthreads();
        }
        int widx = si[0];
        for (int d = tid; d < Hh; d += 256)
            g_emb[b * Hh + d] = embed[widx * Hh + d];
    }
}

// grid 128: l = blk>>6; rb = blk&63 -> 16 d-groups x 4 b-quads(8b); warp k-split
__global__ __launch_bounds__(256) void hatt_kernel(const float* __restrict__ hattb) {
    __shared__ float sX[8*1024];
    __shared__ float sred[256*8];
    int tid = threadIdx.x, blk = blockIdx.x;
    int l = blk >> 6, rb = blk & 63;
    int dg = rb >> 2, bq4 = rb & 3;
    int b0 = bq4*8;
    for (int i = tid; i < 8*1024; i += 256) {
        int b = i >> 10, kk = i & 1023;
        float v = (kk < 512) ? g_attn[(l*Bz + b0 + b)*Hh + kk]
                             : g_h[(l*Bz + b0 + b)*Hh + (kk - 512)];
        sX[i] = v;
    }
    __syncthreads();

    int lane = tid & 31, w = tid >> 5;
    int d = dg*32 + lane;
    float acc[8];
#pragma unroll
    for (int j = 0; j < 8; j++) acc[j] = 0.f;
    int k0 = w*128;
#pragma unroll 2
    for (int kk = k0; kk < k0 + 128; kk += 4) {
        const float* wp = &g_hattWT[kk*Hh + d];
        float w0 = wp[0], w1 = wp[Hh], w2 = wp[2*Hh], w3 = wp[3*Hh];
#pragma unroll
        for (int j = 0; j < 8; j++) {
            float4 a = *(const float4*)&sX[j*1024 + kk];
            acc[j] += a.x*w0 + a.y*w1 + a.z*w2 + a.w*w3;
        }
    }
#pragma unroll
    for (int j = 0; j < 8; j++) sred[(w*32 + lane)*8 + j] = acc[j];
    __syncthreads();

    int d_l = tid >> 3, j = tid & 7;
    float s = 0.f;
#pragma unroll
    for (int w2 = 0; w2 < 8; w2++) s += sred[(w2*32 + d_l)*8 + j];
    int dd = dg*32 + d_l;
    g_hF[(l*Bz + b0 + j)*Hh + dd] = tanhf(s + hattb[dd]);
}

// ---------------- host launcher ----------------
extern "C" void kernel_launch(void* const* d_in, const int* in_sizes, int n_in,
                              void* d_out, int out_size) {
    const float* img    = (const float*)d_in[0];
    const float* pooled = (const float*)d_in[1];
    const float* embed  = (const float*)d_in[2];
    const float* Wq     = (const float*)d_in[3];
    const float* bq     = (const float*)d_in[4];
    const float* Wk     = (const float*)d_in[5];
    const float* bk     = (const float*)d_in[6];
    const float* Wv     = (const float*)d_in[7];
    const float* bv     = (const float*)d_in[8];
    const float* Wih    = (const float*)d_in[9];
    const float* Whh    = (const float*)d_in[10];
    const float* bih    = (const float*)d_in[11];
    const float* bhh    = (const float*)d_in[12];
    const float* projW  = (const float*)d_in[13];
    const float* projb  = (const float*)d_in[14];
    const float* hattW  = (const float*)d_in[15];
    const float* hattb  = (const float*)d_in[16];
    const int*   sos    = (const int*)d_in[17];
    float* res = (float*)d_out;

    const int big_smem = Bz * Hh * (int)sizeof(float);   // 64 KB
    cudaFuncSetAttribute(logits_kernel, cudaFuncAttributeMaxDynamicSharedMemorySize, big_smem);
    cudaFuncSetAttribute(q_kernel,      cudaFuncAttributeMaxDynamicSharedMemorySize, big_smem);

    // launches 1-3 = prep; #6 = gates_kernel(l=1) -> ncu -s 5 -c 1 profiles a real GEMM phase
    prep_transposes<<<592, 256>>>(projW, Wih, Whh, Wq, hattW);
    prep_kv<<<3136, 256>>>(img, Wk, bk, Wv, bv);
    prep_init_t0<<<104, 256>>>(pooled, embed, sos, projb, res);

    for (int t = 0; t < Tt - 1; t++) {
        gates_kernel<<<dim3(32, 4), 256>>>(0);
        cell_kernel<<<Bz, Hh>>>(0, bih, bhh);
        gates_kernel<<<dim3(32, 4), 256>>>(1);
        cell_kernel<<<Bz, Hh>>>(1, bih, bhh);
        logits_kernel<<<(Vv + 63)/64, 256, big_smem>>>(projb, res, t + 1);
        if (t < Tt - 2) {
            q_kernel<<<32, 256, big_smem>>>(bq);
            att_argmax_kernel<<<64, 256>>>(embed);
            hatt_kernel<<<128, 256>>>(hattb);
        }
    }
}

// round 12
// speedup vs baseline: 1.3877x; 1.1164x over previous
#include <cuda_runtime.h>
#include <math.h>

#define Bz 32
#define Hh 512
#define Vv 10000
#define Tt 20
#define Ss 49
#define G4 2048
#define NT_LOG 313          // 32-wide v tiles

// ---------------- device scratch ----------------
__device__ float g_keysT[Bz*Ss*Hh];      // [b][s][d]
__device__ float g_valsSD[Bz*Ss*Hh];     // [b][s][d]
__device__ float g_h[2*Bz*Hh];           // post-cell hidden
__device__ float g_hF[2*Bz*Hh];          // post-attention hidden (recurrent input)
__device__ float g_c[2*Bz*Hh];
__device__ float g_emb[Bz*Hh];
__device__ float g_q[2*Bz*Hh];
__device__ float g_attn[2*Bz*Hh];
__device__ float g_logits[Bz*Vv];
__device__ float g_gpart[8*Bz*G4];       // 8 k-slice partials
__device__ float g_WihT[2*Hh*G4];        // [l][k][j]
__device__ float g_WhhT[2*Hh*G4];
__device__ float g_projWT[Hh*Vv];        // [d][v]
__device__ float g_WqT[Hh*Hh];           // [k][d]
__device__ float g_hattWT[2*Hh*Hh];      // [k][d]

__device__ __forceinline__ float sigm(float x) { return 1.0f / (1.0f + expf(-x)); }

// ================= PREP (unchanged from R11) =================

__global__ void prep_transposes(const float* __restrict__ projW, const float* __restrict__ Wih,
                                const float* __restrict__ Whh,  const float* __restrict__ Wq,
                                const float* __restrict__ hattW) {
    __shared__ float tile[32][33];
    int tx = threadIdx.x & 31, ty = threadIdx.x >> 5;
    for (int task = blockIdx.x; task < 9872; task += gridDim.x) {
        const float* src; float* dst; int R, C, bx, by;
        if (task < 5008)      { src = projW;         dst = g_projWT;       R = Vv; C = Hh;  bx = task % 16; by = task / 16; }
        else if (task < 6032) { int u = task - 5008; src = Wih;            dst = g_WihT;         R = G4; C = Hh;  bx = u % 16; by = u / 16; }
        else if (task < 7056) { int u = task - 6032; src = Wih + G4*Hh;    dst = g_WihT + Hh*G4; R = G4; C = Hh;  bx = u % 16; by = u / 16; }
        else if (task < 8080) { int u = task - 7056; src = Whh;            dst = g_WhhT;         R = G4; C = Hh;  bx = u % 16; by = u / 16; }
        else if (task < 9104) { int u = task - 8080; src = Whh + G4*Hh;    dst = g_WhhT + Hh*G4; R = G4; C = Hh;  bx = u % 16; by = u / 16; }
        else if (task < 9360) { int u = task - 9104; src = Wq;             dst = g_WqT;          R = Hh; C = Hh;  bx = u % 16; by = u / 16; }
        else                  { int u = task - 9360; src = hattW;          dst = g_hattWT;       R = Hh; C = 2*Hh; bx = u % 32; by = u / 32; }
        for (int i = 0; i < 32; i += 8) {
            int r = by*32 + ty + i, c = bx*32 + tx;
            if (r < R && c < C) tile[ty + i][tx] = src[r*C + c];
        }
        __syncthreads();
        for (int i = 0; i < 32; i += 8) {
            int r = by*32 + tx, c = bx*32 + ty + i;
            if (r < R && c < C) dst[c*R + r] = tile[tx][ty + i];
        }
        __syncthreads();
    }
}

__global__ void prep_kv(const float* __restrict__ chan,
                        const float* __restrict__ Wk, const float* __restrict__ bk,
                        const float* __restrict__ Wv, const float* __restrict__ bv) {
    int id = blockIdx.x * 256 + threadIdx.x;
    int d = id & 511;
    int r = id >> 9;
    int s = r % Ss;
    int b = r / Ss;
    const float* cp  = &chan[(b*Hh + d)*Ss];
    const float* wkp = &Wk[s*Ss];
    const float* wvp = &Wv[s*Ss];
    float aK = bk[s], aV = bv[s];
#pragma unroll
    for (int k = 0; k < Ss; k++) { float c = cp[k]; aK += c*wkp[k]; aV += c*wvp[k]; }
    g_keysT[(b*Ss + s)*Hh + d]  = tanhf(aK);
    g_valsSD[(b*Ss + s)*Hh + d] = tanhf(aV);
}

__global__ void prep_init_t0(const float* __restrict__ pooled, const float* __restrict__ embed,
                             const int* __restrict__ sos, const float* __restrict__ projb,
                             float* __restrict__ res) {
    int blk = blockIdx.x, tid = threadIdx.x;
    if (blk < 40) {
        int v = blk*256 + tid;
        if (v < Vv) {
            int sv = sos[0];
            float acc = projb[v];
            for (int d = 0; d < Hh; d++) acc += embed[sv*Hh + d] * g_projWT[d*Vv + v];
            for (int b = 0; b < Bz; b++) res[b*(Vv*Tt) + v*Tt] = acc;
        }
    } else {
        int i = (blk - 40)*256 + tid;
        int d = i & (Hh - 1);
        g_emb[i] = embed[sos[0]*Hh + d];
        float p = pooled[i];
        g_hF[i] = p; g_hF[Bz*Hh + i] = p;
        g_c[i]  = p; g_c[Bz*Hh + i]  = p;
    }
}

// ================= q-GEMM body (dynamic smem, 64KB) =================
__device__ void q_body(int l, int qb, float* sH, const float* __restrict__ bq) {
    int tid = threadIdx.x;
    const float4* h4 = (const float4*)(g_h + l*Bz*Hh);
    float4* s4 = (float4*)sH;
    for (int i = tid; i < Bz*Hh/4; i += 256) s4[i] = h4[i];
    __syncthreads();

    int lane = tid & 31, bg = tid >> 5;
    int d = qb*32 + lane;
    float acc0 = 0.f, acc1 = 0.f, acc2 = 0.f, acc3 = 0.f;
    const float* a0 = &sH[(bg*4 + 0)*Hh];
    const float* a1 = &sH[(bg*4 + 1)*Hh];
    const float* a2 = &sH[(bg*4 + 2)*Hh];
    const float* a3 = &sH[(bg*4 + 3)*Hh];
#pragma unroll 8
    for (int k = 0; k < Hh; k += 4) {
        const float* wp = &g_WqT[k*Hh + d];
        float w0 = wp[0], w1 = wp[Hh], w2 = wp[2*Hh], w3 = wp[3*Hh];
        float4 v0 = *(const float4*)&a0[k];
        float4 v1 = *(const float4*)&a1[k];
        float4 v2 = *(const float4*)&a2[k];
        float4 v3 = *(const float4*)&a3[k];
        acc0 += v0.x*w0 + v0.y*w1 + v0.z*w2 + v0.w*w3;
        acc1 += v1.x*w0 + v1.y*w1 + v1.z*w2 + v1.w*w3;
        acc2 += v2.x*w0 + v2.y*w1 + v2.z*w2 + v2.w*w3;
        acc3 += v3.x*w0 + v3.y*w1 + v3.z*w2 + v3.w*w3;
    }
    float bv = bq[d];
    g_q[(l*Bz + bg*4 + 0)*Hh + d] = tanhf(acc0 + bv);
    g_q[(l*Bz + bg*4 + 1)*Hh + d] = tanhf(acc1 + bv);
    g_q[(l*Bz + bg*4 + 2)*Hh + d] = tanhf(acc2 + bv);
    g_q[(l*Bz + bg*4 + 3)*Hh + d] = tanhf(acc3 + bv);
}

// ================= gates body: 256 blocks (32 j-chunks x 8 k-slices), 16KB smem =================
__device__ void gates_body(int l, int blk, float* S) {
    int tid = threadIdx.x;
    int x = blk & 31, y = blk >> 5;          // x: 64-j chunk, y: 128-k slice
    int ihPart = (y < 4);
    int kbase = (y & 3) * 128;
    const float* src = ihPart ? ((l == 0) ? g_emb : g_h) : (g_hF + l*Bz*Hh);
    float* sh = S;                            // [32 b][128 k]
    for (int i = tid; i < 32*128; i += 256) {
        int b = i >> 7, kk = i & 127;
        sh[b*128 + kk] = src[b*Hh + kbase + kk];
    }
    __syncthreads();

    const float* WT = (ihPart ? g_WihT : g_WhhT) + l*Hh*G4;
    int jl = tid & 63, bg = tid >> 6;
    int j = x*64 + jl;

    float acc0=0,acc1=0,acc2=0,acc3=0,acc4=0,acc5=0,acc6=0,acc7=0;
    const float* shb = &sh[bg*8*128];
#pragma unroll 8
    for (int mi = 0; mi < 128; mi += 4) {
        const float* wp = &WT[(kbase + mi)*G4 + j];
        float w0 = wp[0], w1 = wp[G4], w2 = wp[2*G4], w3 = wp[3*G4];
        float4 v0 = *(const float4*)&shb[0*128 + mi];
        float4 v1 = *(const float4*)&shb[1*128 + mi];
        float4 v2 = *(const float4*)&shb[2*128 + mi];
        float4 v3 = *(const float4*)&shb[3*128 + mi];
        float4 v4 = *(const float4*)&shb[4*128 + mi];
        float4 v5 = *(const float4*)&shb[5*128 + mi];
        float4 v6 = *(const float4*)&shb[6*128 + mi];
        float4 v7 = *(const float4*)&shb[7*128 + mi];
        acc0 += v0.x*w0 + v0.y*w1 + v0.z*w2 + v0.w*w3;
        acc1 += v1.x*w0 + v1.y*w1 + v1.z*w2 + v1.w*w3;
        acc2 += v2.x*w0 + v2.y*w1 + v2.z*w2 + v2.w*w3;
        acc3 += v3.x*w0 + v3.y*w1 + v3.z*w2 + v3.w*w3;
        acc4 += v4.x*w0 + v4.y*w1 + v4.z*w2 + v4.w*w3;
        acc5 += v5.x*w0 + v5.y*w1 + v5.z*w2 + v5.w*w3;
        acc6 += v6.x*w0 + v6.y*w1 + v6.z*w2 + v6.w*w3;
        acc7 += v7.x*w0 + v7.y*w1 + v7.z*w2 + v7.w*w3;
    }
    int bb = bg*8;
    float* gp = &g_gpart[y*32*G4 + j];
    gp[(bb+0)*G4] = acc0; gp[(bb+1)*G4] = acc1;
    gp[(bb+2)*G4] = acc2; gp[(bb+3)*G4] = acc3;
    gp[(bb+4)*G4] = acc4; gp[(bb+5)*G4] = acc5;
    gp[(bb+6)*G4] = acc6; gp[(bb+7)*G4] = acc7;
}

__global__ __launch_bounds__(256) void gates0_kernel() {
    extern __shared__ float S[];
    gates_body(0, blockIdx.x, S);
}

// gates(l=1) blocks 0..255  ||  q(l=0) blocks 256..287
__global__ __launch_bounds__(256) void gates1_q0_kernel(const float* __restrict__ bq) {
    extern __shared__ float S[];
    int blk = blockIdx.x;
    if (blk < 256) gates_body(1, blk, S);
    else           q_body(0, blk - 256, S, bq);
}

// ================= cell: sum 8 partials + elementwise =================
__global__ void cell_kernel(int l, const float* __restrict__ bih,
                            const float* __restrict__ bhh) {
    int b = blockIdx.x, j = threadIdx.x;
    const float* bi = &bih[l * G4];
    const float* bh = &bhh[l * G4];
    float gi = bi[j]        + bh[j];
    float gf = bi[512 + j]  + bh[512 + j];
    float gg = bi[1024 + j] + bh[1024 + j];
    float go = bi[1536 + j] + bh[1536 + j];
#pragma unroll
    for (int ks = 0; ks < 8; ks++) {
        const float* gp = &g_gpart[(ks * 32 + b) * G4];
        gi += gp[j]; gf += gp[512 + j]; gg += gp[1024 + j]; go += gp[1536 + j];
    }
    int idx = (l * Bz + b) * Hh + j;
    float c  = g_c[idx];
    float cn = sigm(gf) * c + sigm(gi) * tanhf(gg);
    g_c[idx] = cn;
    g_h[idx] = sigm(go) * tanhf(cn);
}

// ================= logits: 313 32-v tiles || q(l=1) blocks 313..344 =================
__device__ void logits_body(int tile, float* shl, const float* __restrict__ projb,
                            float* __restrict__ res, int t) {
    int tid = threadIdx.x;
    const float4* H4 = (const float4*)(g_h + Bz*Hh);
    float4* S4 = (float4*)shl;
    for (int i = tid; i < Bz*Hh/4; i += 256) S4[i] = H4[i];
    __syncthreads();

    int vl = tid & 31, bg = tid >> 5;
    int v = tile*32 + vl;
    int vc = (v < Vv) ? v : (Vv - 1);
    bool valid = (v < Vv);

    float acc0=0, acc1=0, acc2=0, acc3=0;
    const float* h0 = &shl[(bg*4 + 0)*Hh];
    const float* h1 = &shl[(bg*4 + 1)*Hh];
    const float* h2 = &shl[(bg*4 + 2)*Hh];
    const float* h3 = &shl[(bg*4 + 3)*Hh];
#pragma unroll 8
    for (int d = 0; d < Hh; d += 4) {
        const float* wp = &g_projWT[d*Vv + vc];
        float w0 = wp[0], w1 = wp[Vv], w2 = wp[2*Vv], w3 = wp[3*Vv];
        float4 a0 = *(const float4*)&h0[d];
        float4 a1 = *(const float4*)&h1[d];
        float4 a2 = *(const float4*)&h2[d];
        float4 a3 = *(const float4*)&h3[d];
        acc0 += a0.x*w0 + a0.y*w1 + a0.z*w2 + a0.w*w3;
        acc1 += a1.x*w0 + a1.y*w1 + a1.z*w2 + a1.w*w3;
        acc2 += a2.x*w0 + a2.y*w1 + a2.z*w2 + a2.w*w3;
        acc3 += a3.x*w0 + a3.y*w1 + a3.z*w2 + a3.w*w3;
    }
    if (valid) {
        float pb = projb[v];
        float a[4] = {acc0, acc1, acc2, acc3};
#pragma unroll
        for (int i = 0; i < 4; i++) {
            int b = bg*4 + i;
            float r = a[i] + pb;
            g_logits[b*Vv + v] = r;
            res[b*(Vv*Tt) + v*Tt + t] = r;
        }
    }
}

__global__ __launch_bounds__(256) void logits_q1_kernel(const float* __restrict__ projb,
                                                        float* __restrict__ res, int t,
                                                        const float* __restrict__ bq,
                                                        int withQ) {
    extern __shared__ float S[];
    int blk = blockIdx.x;
    if (blk < NT_LOG) logits_body(blk, S, projb, res, t);
    else if (withQ)   q_body(1, blk - NT_LOG, S, bq);
}

// ================= att + argmax (R11 body) =================
__global__ __launch_bounds__(256) void att_argmax_kernel(const float* __restrict__ embed) {
    __shared__ float sq[1024];
    __shared__ float ssc[128], sw[128], smax[2], sinv[2];
    __shared__ float sv[256];
    __shared__ int   si[256];
    int tid = threadIdx.x, blk = blockIdx.x;

    if (blk < 32) {
        int l = blk >> 4, b0 = (blk & 15) * 2;
        for (int i = tid; i < 2*Hh; i += 256) {
            int bb = i >> 9;
            sq[i] = g_q[(l*Bz + b0 + bb)*Hh + (i & 511)];
        }
        __syncthreads();

        int warp = tid >> 5, lane = tid & 31;
        int half = warp >> 2, w2 = warp & 3;
        int b = b0 + half;
        for (int s = w2; s < Ss; s += 4) {
            const float* kp = &g_keysT[(b*Ss + s)*Hh];
            const float* qp = &sq[half*Hh];
            float p = 0.f;
            for (int d = lane; d < Hh; d += 32) p += qp[d]*kp[d];
#pragma unroll
            for (int o = 16; o; o >>= 1) p += __shfl_xor_sync(0xffffffffu, p, o);
            if (lane == 0) ssc[half*64 + s] = p * (1.0f/7.0f);
        }
        __syncthreads();
        if (tid < 2) {
            float mx = -INFINITY;
            for (int s = 0; s < Ss; s++) mx = fmaxf(mx, ssc[tid*64 + s]);
            smax[tid] = mx;
        }
        __syncthreads();
        if (tid < 128) {
            int bb = tid >> 6, s = tid & 63;
            if (s < Ss) sw[bb*64 + s] = expf(ssc[bb*64 + s] - smax[bb]);
        }
        __syncthreads();
        if (tid < 2) {
            float sum = 0.f;
            for (int s = 0; s < Ss; s++) sum += sw[tid*64 + s];
            sinv[tid] = 1.0f / sum;
        }
        __syncthreads();
#pragma unroll
        for (int rep = 0; rep < 4; rep++) {
            int idx = rep*256 + tid;
            int bb = idx >> 9, d = idx & 511;
            const float* wv = &sw[bb*64];
            float a = 0.f;
#pragma unroll
            for (int s = 0; s < Ss; s++)
                a += wv[s] * g_valsSD[((b0 + bb)*Ss + s)*Hh + d];
            g_attn[(l*Bz + b0 + bb)*Hh + d] = a * sinv[bb];
        }
    } else {
        int b = blk - 32;
        float best = -INFINITY; int bi = 0;
        for (int v = tid; v < Vv; v += 256) {
            float x = g_logits[b * Vv + v];
            if (x > best) { best = x; bi = v; }
        }
        sv[tid] = best; si[tid] = bi;
        __syncthreads();
        for (int s = 128; s > 0; s >>= 1) {
            if (tid < s) {
                float ov = sv[tid + s]; int oi = si[tid + s];
                if (ov > sv[tid] || (ov == sv[tid] && oi < si[tid])) { sv[tid] = ov; si[tid] = oi; }
            }
            __syncthreads();
        }
        int widx = si[0];
        for (int d = tid; d < Hh; d += 256)
            g_emb[b * Hh + d] = embed[widx * Hh + d];
    }
}

// ================= hatt (R11 body) =================
__global__ __launch_bounds__(256) void hatt_kernel(const float* __restrict__ hattb) {
    __shared__ float sX[8*1024];
    __shared__ float sred[256*8];
    int tid = threadIdx.x, blk = blockIdx.x;
    int l = blk >> 6, rb = blk & 63;
    int dg = rb >> 2, bq4 = rb & 3;
    int b0 = bq4*8;
    for (int i = tid; i < 8*1024; i += 256) {
        int b = i >> 10, kk = i & 1023;
        float v = (kk < 512) ? g_attn[(l*Bz + b0 + b)*Hh + kk]
                             : g_h[(l*Bz + b0 + b)*Hh + (kk - 512)];
        sX[i] = v;
    }
    __syncthreads();

    int lane = tid & 31, w = tid >> 5;
    int d = dg*32 + lane;
    float acc[8];
#pragma unroll
    for (int j = 0; j < 8; j++) acc[j] = 0.f;
    int k0 = w*128;
#pragma unroll 2
    for (int kk = k0; kk < k0 + 128; kk += 4) {
        const float* wp = &g_hattWT[kk*Hh + d];
        float w0 = wp[0], w1 = wp[Hh], w2 = wp[2*Hh], w3 = wp[3*Hh];
#pragma unroll
        for (int j = 0; j < 8; j++) {
            float4 a = *(const float4*)&sX[j*1024 + kk];
            acc[j] += a.x*w0 + a.y*w1 + a.z*w2 + a.w*w3;
        }
    }
#pragma unroll
    for (int j = 0; j < 8; j++) sred[(w*32 + lane)*8 + j] = acc[j];
    __syncthreads();

    int d_l = tid >> 3, j = tid & 7;
    float s = 0.f;
#pragma unroll
    for (int w2 = 0; w2 < 8; w2++) s += sred[(w2*32 + d_l)*8 + j];
    int dd = dg*32 + d_l;
    g_hF[(l*Bz + b0 + j)*Hh + dd] = tanhf(s + hattb[dd]);
}

// ---------------- host launcher ----------------
extern "C" void kernel_launch(void* const* d_in, const int* in_sizes, int n_in,
                              void* d_out, int out_size) {
    const float* img    = (const float*)d_in[0];
    const float* pooled = (const float*)d_in[1];
    const float* embed  = (const float*)d_in[2];
    const float* Wq     = (const float*)d_in[3];
    const float* bq     = (const float*)d_in[4];
    const float* Wk     = (const float*)d_in[5];
    const float* bk     = (const float*)d_in[6];
    const float* Wv     = (const float*)d_in[7];
    const float* bv     = (const float*)d_in[8];
    const float* Wih    = (const float*)d_in[9];
    const float* Whh    = (const float*)d_in[10];
    const float* bih    = (const float*)d_in[11];
    const float* bhh    = (const float*)d_in[12];
    const float* projW  = (const float*)d_in[13];
    const float* projb  = (const float*)d_in[14];
    const float* hattW  = (const float*)d_in[15];
    const float* hattb  = (const float*)d_in[16];
    const int*   sos    = (const int*)d_in[17];
    float* res = (float*)d_out;

    const int big_smem = Bz * Hh * (int)sizeof(float);   // 64 KB (q / logits need it)
    cudaFuncSetAttribute(gates0_kernel,    cudaFuncAttributeMaxDynamicSharedMemorySize, big_smem);
    cudaFuncSetAttribute(gates1_q0_kernel, cudaFuncAttributeMaxDynamicSharedMemorySize, big_smem);
    cudaFuncSetAttribute(logits_q1_kernel, cudaFuncAttributeMaxDynamicSharedMemorySize, big_smem);

    prep_transposes<<<592, 256>>>(projW, Wih, Whh, Wq, hattW);
    prep_kv<<<3136, 256>>>(img, Wk, bk, Wv, bv);
    prep_init_t0<<<104, 256>>>(pooled, embed, sos, projb, res);

    const int gate_smem = 32 * 128 * (int)sizeof(float);  // 16 KB
    for (int t = 0; t < Tt - 1; t++) {
        int withQ = (t < Tt - 2) ? 1 : 0;
        gates0_kernel<<<256, 256, gate_smem>>>();
        cell_kernel<<<Bz, Hh>>>(0, bih, bhh);
        if (withQ) gates1_q0_kernel<<<288, 256, big_smem>>>(bq);
        else       gates1_q0_kernel<<<256, 256, gate_smem>>>(bq);
        cell_kernel<<<Bz, Hh>>>(1, bih, bhh);
        logits_q1_kernel<<<withQ ? 345 : NT_LOG, 256, big_smem>>>(projb, res, t + 1, bq, withQ);
        if (withQ) {
            att_argmax_kernel<<<64, 256>>>(embed);
            hatt_kernel<<<128, 256>>>(hattb);
        }
    }
}